// round 4
// baseline (speedup 1.0000x reference)
#include <cuda_runtime.h>
#include <cuda_fp16.h>
#include <math.h>
#include <stdint.h>

#define BB 4
#define SS 2048
#define DD 1024
#define HH 16
#define DKK 64
#define M_TOTAL (BB*SS)

// Scratch (device globals; allocation-free per harness rules)
__device__ __half g_Qh[BB*HH*SS*DKK];   // [b,h,s,d], pre-scaled by 1/8
__device__ __half g_Kh[BB*HH*SS*DKK];   // [b,h,s,d]
__device__ __half g_Vt[BB*HH*DKK*SS];   // [b,h,d,s]  (transposed V)
__device__ float  g_Ctx[BB*SS*DD];

// ---------------------------------------------------------------------------
// helpers
// ---------------------------------------------------------------------------
__device__ __forceinline__ uint32_t f2tf(float x) {
    uint32_t r;
    asm("cvt.rna.tf32.f32 %0, %1;" : "=r"(r) : "f"(x));
    return r;
}

__device__ __forceinline__ void mma_tf32(float* c, const uint32_t* a, const uint32_t* b) {
    asm volatile(
        "mma.sync.aligned.m16n8k8.row.col.f32.tf32.tf32.f32 "
        "{%0,%1,%2,%3},{%4,%5,%6,%7},{%8,%9},{%0,%1,%2,%3};"
        : "+f"(c[0]), "+f"(c[1]), "+f"(c[2]), "+f"(c[3])
        : "r"(a[0]), "r"(a[1]), "r"(a[2]), "r"(a[3]), "r"(b[0]), "r"(b[1]));
}

__device__ __forceinline__ void mma_f16(float* c, const uint32_t* a,
                                        uint32_t b0, uint32_t b1) {
    asm volatile(
        "mma.sync.aligned.m16n8k16.row.col.f32.f16.f16.f32 "
        "{%0,%1,%2,%3},{%4,%5,%6,%7},{%8,%9},{%0,%1,%2,%3};"
        : "+f"(c[0]), "+f"(c[1]), "+f"(c[2]), "+f"(c[3])
        : "r"(a[0]), "r"(a[1]), "r"(a[2]), "r"(a[3]), "r"(b0), "r"(b1));
}

__device__ __forceinline__ void cp16(void* smem, const void* g) {
    uint32_t s = (uint32_t)__cvta_generic_to_shared(smem);
    asm volatile("cp.async.cg.shared.global [%0], [%1], 16;" :: "r"(s), "l"(g));
}

// swizzled 32-bit shared load: rows are 128B, 16B chunks XORed by row%8
__device__ __forceinline__ uint32_t ldswz(const char* base, int row, int bo) {
    int chunk = bo >> 4, intra = bo & 15;
    return *(const uint32_t*)(base + row * 128 + ((chunk ^ (row & 7)) << 4) + intra);
}

__device__ __forceinline__ uint32_t packh2(float lo, float hi) {
    __half2 h = __floats2half2_rn(lo, hi);
    return *(uint32_t*)&h;
}

// ---------------------------------------------------------------------------
// tf32 tensor-core GEMM: C[m,n] = sum_k A[m,k] * W[n,k]
// EPI 0: fp32 row-major store; EPI 1: RoPE*0.125 -> g_Qh; EPI 2: RoPE -> g_Kh;
// EPI 3: -> g_Vt transposed.
// ---------------------------------------------------------------------------
template<int EPI>
__global__ __launch_bounds__(256)
void gemm_tf32_kernel(const float* __restrict__ A, const float* __restrict__ W,
                      float* __restrict__ Cout, const int* __restrict__ pos)
{
    __shared__ float As[2][128][20];
    __shared__ float Ws[2][128][20];

    const int tid = threadIdx.x;
    const int m0 = blockIdx.y * 128;
    const int n0 = blockIdx.x * 128;
    const int w = tid >> 5, lane = tid & 31;
    const int wm = (w & 1) * 64;
    const int wn = (w >> 1) * 32;
    const int r = lane >> 2, c = lane & 3;

    float acc[4][4][4];
#pragma unroll
    for (int mt = 0; mt < 4; mt++)
#pragma unroll
        for (int nt = 0; nt < 4; nt++)
#pragma unroll
            for (int i = 0; i < 4; i++) acc[mt][nt][i] = 0.f;

    auto load_stage = [&](int buf, int kt) {
        int k0 = kt * 16;
#pragma unroll
        for (int i = 0; i < 2; i++) {
            int idx = tid + i * 256;
            int row = idx >> 2;
            int kc = (idx & 3) * 4;
            cp16(&As[buf][row][kc], A + (size_t)(m0 + row) * DD + k0 + kc);
            cp16(&Ws[buf][row][kc], W + (size_t)(n0 + row) * DD + k0 + kc);
        }
    };

    load_stage(0, 0);
    asm volatile("cp.async.commit_group;");

    int buf = 0;
    const int KT = DD / 16;
    for (int kt = 0; kt < KT; kt++) {
        if (kt + 1 < KT) {
            load_stage(buf ^ 1, kt + 1);
            asm volatile("cp.async.commit_group;");
            asm volatile("cp.async.wait_group 1;");
        } else {
            asm volatile("cp.async.wait_group 0;");
        }
        __syncthreads();

#pragma unroll
        for (int kk = 0; kk < 2; kk++) {
            uint32_t af[4][4];
#pragma unroll
            for (int mt = 0; mt < 4; mt++) {
                int row = wm + mt * 16 + r;
                af[mt][0] = f2tf(As[buf][row][kk * 8 + c]);
                af[mt][1] = f2tf(As[buf][row + 8][kk * 8 + c]);
                af[mt][2] = f2tf(As[buf][row][kk * 8 + c + 4]);
                af[mt][3] = f2tf(As[buf][row + 8][kk * 8 + c + 4]);
            }
            uint32_t bf[4][2];
#pragma unroll
            for (int nt = 0; nt < 4; nt++) {
                int col = wn + nt * 8 + r;
                bf[nt][0] = f2tf(Ws[buf][col][kk * 8 + c]);
                bf[nt][1] = f2tf(Ws[buf][col][kk * 8 + c + 4]);
            }
#pragma unroll
            for (int mt = 0; mt < 4; mt++)
#pragma unroll
                for (int nt = 0; nt < 4; nt++)
                    mma_tf32(acc[mt][nt], af[mt], bf[nt]);
        }
        __syncthreads();
        buf ^= 1;
    }

    // ---------------- epilogue ----------------
    const float LN_TH_OVER = 9.210340372f / 64.0f;  // ln(10000)/64
#pragma unroll
    for (int mt = 0; mt < 4; mt++) {
#pragma unroll
        for (int nt = 0; nt < 4; nt++) {
            int n = n0 + wn + nt * 8 + c * 2;       // even column
#pragma unroll
            for (int half = 0; half < 2; half++) {
                int m = m0 + wm + mt * 16 + r + half * 8;
                float v0 = acc[mt][nt][half * 2];
                float v1 = acc[mt][nt][half * 2 + 1];
                if (EPI == 0) {
                    *(float2*)(Cout + (size_t)m * DD + n) = make_float2(v0, v1);
                } else if (EPI == 3) {
                    int b = m >> 11, s = m & (SS - 1);
                    int h = n >> 6, dk = n & 63;
                    __half* dst = g_Vt + ((size_t)(b * HH + h) * DKK + dk) * SS + s;
                    dst[0]  = __float2half_rn(v0);
                    dst[SS] = __float2half_rn(v1);
                } else {
                    int b = m >> 11, s = m & (SS - 1);
                    int h = n >> 6, dk = n & 63;  // even
                    float p = (float)pos[s];
                    float inv = expf(-(float)dk * LN_TH_OVER);
                    float sn, cs;
                    sincosf(p * inv, &sn, &cs);
                    float o0 = v0 * cs - v1 * sn;
                    float o1 = v0 * sn + v1 * cs;
                    if (EPI == 1) { o0 *= 0.125f; o1 *= 0.125f; }
                    __half* dst = (EPI == 1 ? g_Qh : g_Kh)
                               + (((size_t)(b * HH + h) * SS + s) * DKK + dk);
                    *(uint32_t*)dst = packh2(o0, o1);
                }
            }
        }
    }
}

// ---------------------------------------------------------------------------
// FlashAttention-2 style fp16 tensor-core attention.
// Block: 128 Q rows, 8 warps (16 rows each). KV tile 64. Causal.
// K smem: [kv][d] natural; V smem: [d][kv] (g_Vt already transposed).
// 128B rows with XOR-16B swizzle, cp.async double buffered.
// ---------------------------------------------------------------------------
__global__ __launch_bounds__(256, 2)
void attn_kernel()
{
    __shared__ __align__(16) char sK[2][64 * 128];
    __shared__ __align__(16) char sV[2][64 * 128];

    const int qt = (int)gridDim.x - 1 - (int)blockIdx.x;  // heavy tiles first
    const int h  = blockIdx.y;
    const int b  = blockIdx.z;
    const int tid = threadIdx.x;
    const int w = tid >> 5, lane = tid & 31;
    const int g = lane >> 2, c = lane & 3;
    const int q0w = qt * 128 + w * 16;    // this warp's first Q row

    const __half* Qbh = g_Qh + (size_t)(b * HH + h) * SS * DKK;
    const __half* Kbh = g_Kh + (size_t)(b * HH + h) * SS * DKK;
    const __half* Vbh = g_Vt + (size_t)(b * HH + h) * DKK * SS;

    // Q fragments in registers for the whole kernel (already scaled by 1/8)
    uint32_t qreg[4][4];
#pragma unroll
    for (int kk = 0; kk < 4; kk++) {
        qreg[kk][0] = *(const uint32_t*)(Qbh + (q0w + g) * DKK + 16 * kk + 2 * c);
        qreg[kk][1] = *(const uint32_t*)(Qbh + (q0w + g + 8) * DKK + 16 * kk + 2 * c);
        qreg[kk][2] = *(const uint32_t*)(Qbh + (q0w + g) * DKK + 16 * kk + 2 * c + 8);
        qreg[kk][3] = *(const uint32_t*)(Qbh + (q0w + g + 8) * DKK + 16 * kk + 2 * c + 8);
    }

    float Oc[8][4];
#pragma unroll
    for (int n = 0; n < 8; n++)
#pragma unroll
        for (int i = 0; i < 4; i++) Oc[n][i] = 0.f;
    float mrow[2] = {-1e30f, -1e30f};
    float lrow[2] = {0.f, 0.f};

    auto load_kv = [&](int bufi, int kt) {
        int kv0 = kt * 64;
#pragma unroll
        for (int i = 0; i < 2; i++) {
            int idx = tid + i * 256;          // 0..511
            int r = idx >> 3;                 // 0..63
            int ch = idx & 7;                 // 16B chunk
            int dst = r * 128 + ((ch ^ (r & 7)) << 4);
            cp16(sK[bufi] + dst, Kbh + (size_t)(kv0 + r) * DKK + ch * 8);
            cp16(sV[bufi] + dst, Vbh + (size_t)r * SS + kv0 + ch * 8);
        }
    };

    const int ktmax = qt * 2 + 1;
    load_kv(0, 0);
    asm volatile("cp.async.commit_group;");

    int buf = 0;
    for (int kt = 0; kt <= ktmax; kt++) {
        if (kt < ktmax) {
            load_kv(buf ^ 1, kt + 1);
            asm volatile("cp.async.commit_group;");
            asm volatile("cp.async.wait_group 1;");
        } else {
            asm volatile("cp.async.wait_group 0;");
        }
        __syncthreads();

        const int kv0 = kt * 64;

        // ---- S = Q K^T ----
        float Sc[8][4];
#pragma unroll
        for (int n = 0; n < 8; n++)
#pragma unroll
            for (int i = 0; i < 4; i++) Sc[n][i] = 0.f;

#pragma unroll
        for (int n = 0; n < 8; n++) {
#pragma unroll
            for (int kk = 0; kk < 4; kk++) {
                uint32_t b0 = ldswz(sK[buf], n * 8 + g, 32 * kk + 4 * c);
                uint32_t b1 = ldswz(sK[buf], n * 8 + g, 32 * kk + 16 + 4 * c);
                mma_f16(Sc[n], qreg[kk], b0, b1);
            }
        }

        // ---- causal mask (only on diagonal-touching tiles for this warp) ----
        if (kv0 + 63 > q0w) {
            int r0 = q0w + g, r1 = q0w + g + 8;
#pragma unroll
            for (int n = 0; n < 8; n++) {
                int col = kv0 + n * 8 + 2 * c;
                if (col > r0)     Sc[n][0] = -1e30f;
                if (col + 1 > r0) Sc[n][1] = -1e30f;
                if (col > r1)     Sc[n][2] = -1e30f;
                if (col + 1 > r1) Sc[n][3] = -1e30f;
            }
        }

        // ---- online softmax (rows g and g+8; quad reduce over lanes) ----
        float mx0 = Sc[0][0], mx1 = Sc[0][2];
#pragma unroll
        for (int n = 0; n < 8; n++) {
            mx0 = fmaxf(mx0, fmaxf(Sc[n][0], Sc[n][1]));
            mx1 = fmaxf(mx1, fmaxf(Sc[n][2], Sc[n][3]));
        }
        mx0 = fmaxf(mx0, __shfl_xor_sync(0xffffffffu, mx0, 1));
        mx0 = fmaxf(mx0, __shfl_xor_sync(0xffffffffu, mx0, 2));
        mx1 = fmaxf(mx1, __shfl_xor_sync(0xffffffffu, mx1, 1));
        mx1 = fmaxf(mx1, __shfl_xor_sync(0xffffffffu, mx1, 2));

        float mn0 = fmaxf(mrow[0], mx0);
        float mn1 = fmaxf(mrow[1], mx1);
        float a0 = __expf(mrow[0] - mn0);
        float a1 = __expf(mrow[1] - mn1);

        float rs0 = 0.f, rs1 = 0.f;
#pragma unroll
        for (int n = 0; n < 8; n++) {
            Sc[n][0] = __expf(Sc[n][0] - mn0);
            Sc[n][1] = __expf(Sc[n][1] - mn0);
            Sc[n][2] = __expf(Sc[n][2] - mn1);
            Sc[n][3] = __expf(Sc[n][3] - mn1);
            rs0 += Sc[n][0] + Sc[n][1];
            rs1 += Sc[n][2] + Sc[n][3];
        }
        rs0 += __shfl_xor_sync(0xffffffffu, rs0, 1);
        rs0 += __shfl_xor_sync(0xffffffffu, rs0, 2);
        rs1 += __shfl_xor_sync(0xffffffffu, rs1, 1);
        rs1 += __shfl_xor_sync(0xffffffffu, rs1, 2);

        lrow[0] = lrow[0] * a0 + rs0;
        lrow[1] = lrow[1] * a1 + rs1;
        mrow[0] = mn0; mrow[1] = mn1;

#pragma unroll
        for (int n = 0; n < 8; n++) {
            Oc[n][0] *= a0; Oc[n][1] *= a0;
            Oc[n][2] *= a1; Oc[n][3] *= a1;
        }

        // ---- pack P into A fragments (C layout == A layout for f16 k16) ----
        uint32_t pa[4][4];
#pragma unroll
        for (int kk = 0; kk < 4; kk++) {
            pa[kk][0] = packh2(Sc[2 * kk][0],     Sc[2 * kk][1]);
            pa[kk][1] = packh2(Sc[2 * kk][2],     Sc[2 * kk][3]);
            pa[kk][2] = packh2(Sc[2 * kk + 1][0], Sc[2 * kk + 1][1]);
            pa[kk][3] = packh2(Sc[2 * kk + 1][2], Sc[2 * kk + 1][3]);
        }

        // ---- O += P V ----
#pragma unroll
        for (int nd = 0; nd < 8; nd++) {
#pragma unroll
            for (int kk = 0; kk < 4; kk++) {
                uint32_t b0 = ldswz(sV[buf], nd * 8 + g, 32 * kk + 4 * c);
                uint32_t b1 = ldswz(sV[buf], nd * 8 + g, 32 * kk + 16 + 4 * c);
                mma_f16(Oc[nd], pa[kk], b0, b1);
            }
        }

        __syncthreads();
        buf ^= 1;
    }

    // ---- finalize, write context fp32 [b,s,D] ----
    float inv0 = 1.f / lrow[0];
    float inv1 = 1.f / lrow[1];
    float* Cb0 = g_Ctx + ((size_t)(b * SS + q0w + g) * DD + h * 64);
    float* Cb1 = g_Ctx + ((size_t)(b * SS + q0w + g + 8) * DD + h * 64);
#pragma unroll
    for (int nd = 0; nd < 8; nd++) {
        int col = nd * 8 + 2 * c;
        *(float2*)(Cb0 + col) = make_float2(Oc[nd][0] * inv0, Oc[nd][1] * inv0);
        *(float2*)(Cb1 + col) = make_float2(Oc[nd][2] * inv1, Oc[nd][3] * inv1);
    }
}

// ---------------------------------------------------------------------------
extern "C" void kernel_launch(void* const* d_in, const int* in_sizes, int n_in,
                              void* d_out, int out_size)
{
    const float* x  = (const float*)d_in[0];
    const float* Wq = (const float*)d_in[1];
    const float* Wk = (const float*)d_in[2];
    const float* Wv = (const float*)d_in[3];
    const float* Wo = (const float*)d_in[4];
    const int* pos  = (const int*)d_in[5];
    float* out = (float*)d_out;

    void* ctx_ptr = nullptr;
    cudaGetSymbolAddress(&ctx_ptr, g_Ctx);

    dim3 ggrid(DD / 128, M_TOTAL / 128);   // 8 x 64

    gemm_tf32_kernel<1><<<ggrid, 256>>>(x, Wq, nullptr, pos);
    gemm_tf32_kernel<2><<<ggrid, 256>>>(x, Wk, nullptr, pos);
    gemm_tf32_kernel<3><<<ggrid, 256>>>(x, Wv, nullptr, pos);

    dim3 agrid(SS / 128, HH, BB);
    attn_kernel<<<agrid, 256>>>();

    gemm_tf32_kernel<0><<<ggrid, 256>>>((const float*)ctx_ptr, Wo, out, pos);
}

// round 5
// speedup vs baseline: 1.4150x; 1.4150x over previous
#include <cuda_runtime.h>
#include <cuda_fp16.h>
#include <math.h>
#include <stdint.h>

#define BB 4
#define SS 2048
#define DD 1024
#define HH 16
#define DKK 64
#define M_TOTAL (BB*SS)

// Scratch (device globals; allocation-free per harness rules)
__device__ __half g_xh [M_TOTAL*DD];     // fp16 copy of x
__device__ __half g_Wh [4*DD*DD];        // fp16 copies of Wq,Wk,Wv,Wo
__device__ __half g_Qh [BB*HH*SS*DKK];   // [b,h,s,d], pre-scaled by 1/8
__device__ __half g_Kh [BB*HH*SS*DKK];   // [b,h,s,d]
__device__ __half g_Vt [BB*HH*DKK*SS];   // [b,h,d,s]  (transposed V)
__device__ __half g_Ctxh[M_TOTAL*DD];    // fp16 context [b,s,D]

// ---------------------------------------------------------------------------
// helpers
// ---------------------------------------------------------------------------
__device__ __forceinline__ void mma_f16(float* c, const uint32_t* a,
                                        uint32_t b0, uint32_t b1) {
    asm volatile(
        "mma.sync.aligned.m16n8k16.row.col.f32.f16.f16.f32 "
        "{%0,%1,%2,%3},{%4,%5,%6,%7},{%8,%9},{%0,%1,%2,%3};"
        : "+f"(c[0]), "+f"(c[1]), "+f"(c[2]), "+f"(c[3])
        : "r"(a[0]), "r"(a[1]), "r"(a[2]), "r"(a[3]), "r"(b0), "r"(b1));
}

__device__ __forceinline__ void cp16(void* smem, const void* g) {
    uint32_t s = (uint32_t)__cvta_generic_to_shared(smem);
    asm volatile("cp.async.cg.shared.global [%0], [%1], 16;" :: "r"(s), "l"(g));
}

// swizzled 32-bit shared load: rows are 128B, 16B chunks XORed by row%8
__device__ __forceinline__ uint32_t ldswz(const char* base, int row, int bo) {
    int chunk = bo >> 4, intra = bo & 15;
    return *(const uint32_t*)(base + row * 128 + ((chunk ^ (row & 7)) << 4) + intra);
}

__device__ __forceinline__ uint32_t packh2(float lo, float hi) {
    __half2 h = __floats2half2_rn(lo, hi);
    return *(uint32_t*)&h;
}

// ---------------------------------------------------------------------------
// fp32 -> fp16 conversion (grid-stride over float4)
// ---------------------------------------------------------------------------
__global__ void cvt_kernel(const float* __restrict__ src, __half* __restrict__ dst,
                           int n4)
{
    int i = blockIdx.x * blockDim.x + threadIdx.x;
    for (; i < n4; i += gridDim.x * blockDim.x) {
        float4 v = ((const float4*)src)[i];
        uint32_t lo = packh2(v.x, v.y);
        uint32_t hi = packh2(v.z, v.w);
        ((uint2*)dst)[i] = make_uint2(lo, hi);
    }
}

// ---------------------------------------------------------------------------
// fp16 tensor-core GEMM: C[m,n] = sum_k A[m,k] * W[n,k]  (A,W fp16, acc fp32)
// Block tile 128x128, K-chunk 32, double-buffered cp.async.
// 8 warps: 2(M) x 4(N), warp tile 64x32 (4x4 m16n8k16, 2 k-steps/chunk).
// Smem rows padded to 40 halfs (80B) -> conflict-free 32-bit fragment loads.
// EPI 0: fp32 row-major store; EPI 1: RoPE*0.125 -> g_Qh; EPI 2: RoPE -> g_Kh;
// EPI 3: -> g_Vt transposed.
// ---------------------------------------------------------------------------
template<int EPI>
__global__ __launch_bounds__(256)
void gemm_f16_kernel(const __half* __restrict__ A, const __half* __restrict__ W,
                     float* __restrict__ Cout, const int* __restrict__ pos)
{
    __shared__ __half As[2][128][40];
    __shared__ __half Ws[2][128][40];

    const int tid = threadIdx.x;
    const int m0 = blockIdx.y * 128;
    const int n0 = blockIdx.x * 128;
    const int w = tid >> 5, lane = tid & 31;
    const int wm = (w & 1) * 64;
    const int wn = (w >> 1) * 32;
    const int r = lane >> 2, c = lane & 3;

    float acc[4][4][4];
#pragma unroll
    for (int mt = 0; mt < 4; mt++)
#pragma unroll
        for (int nt = 0; nt < 4; nt++)
#pragma unroll
            for (int i = 0; i < 4; i++) acc[mt][nt][i] = 0.f;

    // stage: 128 rows x 32 halfs (4x 16B chunks) per matrix
    auto load_stage = [&](int buf, int kt) {
        int k0 = kt * 32;
#pragma unroll
        for (int i = 0; i < 2; i++) {
            int idx = tid + i * 256;       // 0..511
            int row = idx >> 2;            // 0..127
            int ch = (idx & 3) * 8;        // half offset 0,8,16,24
            cp16(&As[buf][row][ch], A + (size_t)(m0 + row) * DD + k0 + ch);
            cp16(&Ws[buf][row][ch], W + (size_t)(n0 + row) * DD + k0 + ch);
        }
    };

    load_stage(0, 0);
    asm volatile("cp.async.commit_group;");

    int buf = 0;
    const int KT = DD / 32;  // 32
    for (int kt = 0; kt < KT; kt++) {
        if (kt + 1 < KT) {
            load_stage(buf ^ 1, kt + 1);
            asm volatile("cp.async.commit_group;");
            asm volatile("cp.async.wait_group 1;");
        } else {
            asm volatile("cp.async.wait_group 0;");
        }
        __syncthreads();

#pragma unroll
        for (int kk = 0; kk < 2; kk++) {
            uint32_t af[4][4];
#pragma unroll
            for (int mt = 0; mt < 4; mt++) {
                int row = wm + mt * 16 + r;
                af[mt][0] = *(const uint32_t*)&As[buf][row][kk * 16 + 2 * c];
                af[mt][1] = *(const uint32_t*)&As[buf][row + 8][kk * 16 + 2 * c];
                af[mt][2] = *(const uint32_t*)&As[buf][row][kk * 16 + 2 * c + 8];
                af[mt][3] = *(const uint32_t*)&As[buf][row + 8][kk * 16 + 2 * c + 8];
            }
            uint32_t bf[4][2];
#pragma unroll
            for (int nt = 0; nt < 4; nt++) {
                int col = wn + nt * 8 + r;
                bf[nt][0] = *(const uint32_t*)&Ws[buf][col][kk * 16 + 2 * c];
                bf[nt][1] = *(const uint32_t*)&Ws[buf][col][kk * 16 + 2 * c + 8];
            }
#pragma unroll
            for (int mt = 0; mt < 4; mt++)
#pragma unroll
                for (int nt = 0; nt < 4; nt++)
                    mma_f16(acc[mt][nt], af[mt], bf[nt][0], bf[nt][1]);
        }
        __syncthreads();
        buf ^= 1;
    }

    // ---------------- epilogue ----------------
    const float LN_TH_OVER = 9.210340372f / 64.0f;  // ln(10000)/64
#pragma unroll
    for (int mt = 0; mt < 4; mt++) {
#pragma unroll
        for (int nt = 0; nt < 4; nt++) {
            int n = n0 + wn + nt * 8 + c * 2;       // even column
#pragma unroll
            for (int half = 0; half < 2; half++) {
                int m = m0 + wm + mt * 16 + r + half * 8;
                float v0 = acc[mt][nt][half * 2];
                float v1 = acc[mt][nt][half * 2 + 1];
                if (EPI == 0) {
                    *(float2*)(Cout + (size_t)m * DD + n) = make_float2(v0, v1);
                } else if (EPI == 3) {
                    int b = m >> 11, s = m & (SS - 1);
                    int h = n >> 6, dk = n & 63;
                    __half* dst = g_Vt + ((size_t)(b * HH + h) * DKK + dk) * SS + s;
                    dst[0]  = __float2half_rn(v0);
                    dst[SS] = __float2half_rn(v1);
                } else {
                    int b = m >> 11, s = m & (SS - 1);
                    int h = n >> 6, dk = n & 63;  // even
                    float p = (float)pos[s];
                    float inv = expf(-(float)dk * LN_TH_OVER);
                    float sn, cs;
                    sincosf(p * inv, &sn, &cs);
                    float o0 = v0 * cs - v1 * sn;
                    float o1 = v0 * sn + v1 * cs;
                    if (EPI == 1) { o0 *= 0.125f; o1 *= 0.125f; }
                    __half* dst = (EPI == 1 ? g_Qh : g_Kh)
                               + (((size_t)(b * HH + h) * SS + s) * DKK + dk);
                    *(uint32_t*)dst = packh2(o0, o1);
                }
            }
        }
    }
}

// ---------------------------------------------------------------------------
// FlashAttention-2 style fp16 tensor-core attention (ctx now stored fp16).
// ---------------------------------------------------------------------------
__global__ __launch_bounds__(256, 2)
void attn_kernel()
{
    __shared__ __align__(16) char sK[2][64 * 128];
    __shared__ __align__(16) char sV[2][64 * 128];

    const int qt = (int)gridDim.x - 1 - (int)blockIdx.x;  // heavy tiles first
    const int h  = blockIdx.y;
    const int b  = blockIdx.z;
    const int tid = threadIdx.x;
    const int w = tid >> 5, lane = tid & 31;
    const int g = lane >> 2, c = lane & 3;
    const int q0w = qt * 128 + w * 16;    // this warp's first Q row

    const __half* Qbh = g_Qh + (size_t)(b * HH + h) * SS * DKK;
    const __half* Kbh = g_Kh + (size_t)(b * HH + h) * SS * DKK;
    const __half* Vbh = g_Vt + (size_t)(b * HH + h) * DKK * SS;

    uint32_t qreg[4][4];
#pragma unroll
    for (int kk = 0; kk < 4; kk++) {
        qreg[kk][0] = *(const uint32_t*)(Qbh + (q0w + g) * DKK + 16 * kk + 2 * c);
        qreg[kk][1] = *(const uint32_t*)(Qbh + (q0w + g + 8) * DKK + 16 * kk + 2 * c);
        qreg[kk][2] = *(const uint32_t*)(Qbh + (q0w + g) * DKK + 16 * kk + 2 * c + 8);
        qreg[kk][3] = *(const uint32_t*)(Qbh + (q0w + g + 8) * DKK + 16 * kk + 2 * c + 8);
    }

    float Oc[8][4];
#pragma unroll
    for (int n = 0; n < 8; n++)
#pragma unroll
        for (int i = 0; i < 4; i++) Oc[n][i] = 0.f;
    float mrow[2] = {-1e30f, -1e30f};
    float lrow[2] = {0.f, 0.f};

    auto load_kv = [&](int bufi, int kt) {
        int kv0 = kt * 64;
#pragma unroll
        for (int i = 0; i < 2; i++) {
            int idx = tid + i * 256;          // 0..511
            int r = idx >> 3;                 // 0..63
            int ch = idx & 7;                 // 16B chunk
            int dst = r * 128 + ((ch ^ (r & 7)) << 4);
            cp16(sK[bufi] + dst, Kbh + (size_t)(kv0 + r) * DKK + ch * 8);
            cp16(sV[bufi] + dst, Vbh + (size_t)r * SS + kv0 + ch * 8);
        }
    };

    const int ktmax = qt * 2 + 1;
    load_kv(0, 0);
    asm volatile("cp.async.commit_group;");

    int buf = 0;
    for (int kt = 0; kt <= ktmax; kt++) {
        if (kt < ktmax) {
            load_kv(buf ^ 1, kt + 1);
            asm volatile("cp.async.commit_group;");
            asm volatile("cp.async.wait_group 1;");
        } else {
            asm volatile("cp.async.wait_group 0;");
        }
        __syncthreads();

        const int kv0 = kt * 64;

        float Sc[8][4];
#pragma unroll
        for (int n = 0; n < 8; n++)
#pragma unroll
            for (int i = 0; i < 4; i++) Sc[n][i] = 0.f;

#pragma unroll
        for (int n = 0; n < 8; n++) {
#pragma unroll
            for (int kk = 0; kk < 4; kk++) {
                uint32_t b0 = ldswz(sK[buf], n * 8 + g, 32 * kk + 4 * c);
                uint32_t b1 = ldswz(sK[buf], n * 8 + g, 32 * kk + 16 + 4 * c);
                mma_f16(Sc[n], qreg[kk], b0, b1);
            }
        }

        if (kv0 + 63 > q0w) {
            int r0 = q0w + g, r1 = q0w + g + 8;
#pragma unroll
            for (int n = 0; n < 8; n++) {
                int col = kv0 + n * 8 + 2 * c;
                if (col > r0)     Sc[n][0] = -1e30f;
                if (col + 1 > r0) Sc[n][1] = -1e30f;
                if (col > r1)     Sc[n][2] = -1e30f;
                if (col + 1 > r1) Sc[n][3] = -1e30f;
            }
        }

        float mx0 = Sc[0][0], mx1 = Sc[0][2];
#pragma unroll
        for (int n = 0; n < 8; n++) {
            mx0 = fmaxf(mx0, fmaxf(Sc[n][0], Sc[n][1]));
            mx1 = fmaxf(mx1, fmaxf(Sc[n][2], Sc[n][3]));
        }
        mx0 = fmaxf(mx0, __shfl_xor_sync(0xffffffffu, mx0, 1));
        mx0 = fmaxf(mx0, __shfl_xor_sync(0xffffffffu, mx0, 2));
        mx1 = fmaxf(mx1, __shfl_xor_sync(0xffffffffu, mx1, 1));
        mx1 = fmaxf(mx1, __shfl_xor_sync(0xffffffffu, mx1, 2));

        float mn0 = fmaxf(mrow[0], mx0);
        float mn1 = fmaxf(mrow[1], mx1);
        float a0 = __expf(mrow[0] - mn0);
        float a1 = __expf(mrow[1] - mn1);

        float rs0 = 0.f, rs1 = 0.f;
#pragma unroll
        for (int n = 0; n < 8; n++) {
            Sc[n][0] = __expf(Sc[n][0] - mn0);
            Sc[n][1] = __expf(Sc[n][1] - mn0);
            Sc[n][2] = __expf(Sc[n][2] - mn1);
            Sc[n][3] = __expf(Sc[n][3] - mn1);
            rs0 += Sc[n][0] + Sc[n][1];
            rs1 += Sc[n][2] + Sc[n][3];
        }
        rs0 += __shfl_xor_sync(0xffffffffu, rs0, 1);
        rs0 += __shfl_xor_sync(0xffffffffu, rs0, 2);
        rs1 += __shfl_xor_sync(0xffffffffu, rs1, 1);
        rs1 += __shfl_xor_sync(0xffffffffu, rs1, 2);

        lrow[0] = lrow[0] * a0 + rs0;
        lrow[1] = lrow[1] * a1 + rs1;
        mrow[0] = mn0; mrow[1] = mn1;

#pragma unroll
        for (int n = 0; n < 8; n++) {
            Oc[n][0] *= a0; Oc[n][1] *= a0;
            Oc[n][2] *= a1; Oc[n][3] *= a1;
        }

        uint32_t pa[4][4];
#pragma unroll
        for (int kk = 0; kk < 4; kk++) {
            pa[kk][0] = packh2(Sc[2 * kk][0],     Sc[2 * kk][1]);
            pa[kk][1] = packh2(Sc[2 * kk][2],     Sc[2 * kk][3]);
            pa[kk][2] = packh2(Sc[2 * kk + 1][0], Sc[2 * kk + 1][1]);
            pa[kk][3] = packh2(Sc[2 * kk + 1][2], Sc[2 * kk + 1][3]);
        }

#pragma unroll
        for (int nd = 0; nd < 8; nd++) {
#pragma unroll
            for (int kk = 0; kk < 4; kk++) {
                uint32_t b0 = ldswz(sV[buf], nd * 8 + g, 32 * kk + 4 * c);
                uint32_t b1 = ldswz(sV[buf], nd * 8 + g, 32 * kk + 16 + 4 * c);
                mma_f16(Oc[nd], pa[kk], b0, b1);
            }
        }

        __syncthreads();
        buf ^= 1;
    }

    // ---- finalize, write context fp16 [b,s,D] ----
    float inv0 = 1.f / lrow[0];
    float inv1 = 1.f / lrow[1];
    __half* Cb0 = g_Ctxh + ((size_t)(b * SS + q0w + g) * DD + h * 64);
    __half* Cb1 = g_Ctxh + ((size_t)(b * SS + q0w + g + 8) * DD + h * 64);
#pragma unroll
    for (int nd = 0; nd < 8; nd++) {
        int col = nd * 8 + 2 * c;
        *(uint32_t*)(Cb0 + col) = packh2(Oc[nd][0] * inv0, Oc[nd][1] * inv0);
        *(uint32_t*)(Cb1 + col) = packh2(Oc[nd][2] * inv1, Oc[nd][3] * inv1);
    }
}

// ---------------------------------------------------------------------------
extern "C" void kernel_launch(void* const* d_in, const int* in_sizes, int n_in,
                              void* d_out, int out_size)
{
    const float* x  = (const float*)d_in[0];
    const float* Wq = (const float*)d_in[1];
    const float* Wk = (const float*)d_in[2];
    const float* Wv = (const float*)d_in[3];
    const float* Wo = (const float*)d_in[4];
    const int* pos  = (const int*)d_in[5];
    float* out = (float*)d_out;

    void* xh_ptr = nullptr, *wh_ptr = nullptr, *ctxh_ptr = nullptr;
    cudaGetSymbolAddress(&xh_ptr, g_xh);
    cudaGetSymbolAddress(&wh_ptr, g_Wh);
    cudaGetSymbolAddress(&ctxh_ptr, g_Ctxh);
    __half* xh = (__half*)xh_ptr;
    __half* wh = (__half*)wh_ptr;

    // fp32 -> fp16 conversions
    cvt_kernel<<<2048, 256>>>(x,  xh,            M_TOTAL * DD / 4);
    cvt_kernel<<<512, 256>>>(Wq, wh + 0*DD*DD,   DD * DD / 4);
    cvt_kernel<<<512, 256>>>(Wk, wh + 1*DD*DD,   DD * DD / 4);
    cvt_kernel<<<512, 256>>>(Wv, wh + 2*DD*DD,   DD * DD / 4);
    cvt_kernel<<<512, 256>>>(Wo, wh + 3*DD*DD,   DD * DD / 4);

    dim3 ggrid(DD / 128, M_TOTAL / 128);   // 8 x 64

    gemm_f16_kernel<1><<<ggrid, 256>>>(xh, wh + 0*DD*DD, nullptr, pos);
    gemm_f16_kernel<2><<<ggrid, 256>>>(xh, wh + 1*DD*DD, nullptr, pos);
    gemm_f16_kernel<3><<<ggrid, 256>>>(xh, wh + 2*DD*DD, nullptr, pos);

    dim3 agrid(SS / 128, HH, BB);
    attn_kernel<<<agrid, 256>>>();

    gemm_f16_kernel<0><<<ggrid, 256>>>((const __half*)ctxh_ptr, wh + 3*DD*DD,
                                       out, pos);
}

// round 7
// speedup vs baseline: 1.6247x; 1.1482x over previous
#include <cuda_runtime.h>
#include <cuda_fp16.h>
#include <math.h>
#include <stdint.h>

#define BB 4
#define SS 2048
#define DD 1024
#define HH 16
#define DKK 64
#define M_TOTAL (BB*SS)

// Scratch (device globals; allocation-free per harness rules)
__device__ __half g_xh [M_TOTAL*DD];     // fp16 copy of x
__device__ __half g_Wh [4*DD*DD];        // fp16 copies of Wq,Wk,Wv,Wo
__device__ __half g_Qh [BB*HH*SS*DKK];   // [b,h,s,d], pre-scaled by 1/8
__device__ __half g_Kh [BB*HH*SS*DKK];   // [b,h,s,d]
__device__ __half g_Vt [BB*HH*DKK*SS];   // [b,h,d,s]  (transposed V)
__device__ __half g_Ctxh[M_TOTAL*DD];    // fp16 context [b,s,D]

// ---------------------------------------------------------------------------
// helpers
// ---------------------------------------------------------------------------
__device__ __forceinline__ uint32_t smem_u32(const void* p) {
    uint32_t a;
    asm("{ .reg .u64 t; cvta.to.shared.u64 t, %1; cvt.u32.u64 %0, t; }"
        : "=r"(a) : "l"(p));
    return a;
}

__device__ __forceinline__ void mma_f16(float* c, const uint32_t* a,
                                        uint32_t b0, uint32_t b1) {
    asm volatile(
        "mma.sync.aligned.m16n8k16.row.col.f32.f16.f16.f32 "
        "{%0,%1,%2,%3},{%4,%5,%6,%7},{%8,%9},{%0,%1,%2,%3};"
        : "+f"(c[0]), "+f"(c[1]), "+f"(c[2]), "+f"(c[3])
        : "r"(a[0]), "r"(a[1]), "r"(a[2]), "r"(a[3]), "r"(b0), "r"(b1));
}

__device__ __forceinline__ void ldsm_x4(uint32_t& r0, uint32_t& r1,
                                        uint32_t& r2, uint32_t& r3, uint32_t addr) {
    asm volatile("ldmatrix.sync.aligned.m8n8.x4.shared.b16 {%0,%1,%2,%3}, [%4];"
                 : "=r"(r0), "=r"(r1), "=r"(r2), "=r"(r3) : "r"(addr));
}

__device__ __forceinline__ void cp16(void* smem, const void* g) {
    uint32_t s = smem_u32(smem);
    asm volatile("cp.async.cg.shared.global [%0], [%1], 16;" :: "r"(s), "l"(g));
}

__device__ __forceinline__ uint32_t packh2(float lo, float hi) {
    __half2 h = __floats2half2_rn(lo, hi);
    return *(uint32_t*)&h;
}

// ---------------------------------------------------------------------------
// fp32 -> fp16 conversions
// ---------------------------------------------------------------------------
__global__ void cvt_kernel(const float* __restrict__ src, __half* __restrict__ dst,
                           int n4)
{
    int i = blockIdx.x * blockDim.x + threadIdx.x;
    for (; i < n4; i += gridDim.x * blockDim.x) {
        float4 v = ((const float4*)src)[i];
        ((uint2*)dst)[i] = make_uint2(packh2(v.x, v.y), packh2(v.z, v.w));
    }
}

__global__ void cvtw_kernel(const float* W0, const float* W1,
                            const float* W2, const float* W3, int n4)
{
    const float* src = blockIdx.z == 0 ? W0 : blockIdx.z == 1 ? W1
                     : blockIdx.z == 2 ? W2 : W3;
    __half* dst = g_Wh + (size_t)blockIdx.z * DD * DD;
    int i = blockIdx.x * blockDim.x + threadIdx.x;
    for (; i < n4; i += gridDim.x * blockDim.x) {
        float4 v = ((const float4*)src)[i];
        ((uint2*)dst)[i] = make_uint2(packh2(v.x, v.y), packh2(v.z, v.w));
    }
}

// ---------------------------------------------------------------------------
// fp16 tensor-core GEMM (HMMA + LDSM): C[m,n] = sum_k A[m,k] * W[n,k]
// Block tile 128x128, K-chunk 32, double-buffered cp.async.
// 8 warps: 2(M) x 4(N), warp tile 64x32 (4x4 m16n8k16, 2 k-steps/chunk).
// Smem rows 40 halfs (80B pitch) -> LDSM-conflict-free.
// ---------------------------------------------------------------------------
template<int EPI>
__global__ __launch_bounds__(256)
void gemm_f16_kernel(const __half* __restrict__ A, const __half* __restrict__ W,
                     float* __restrict__ Cout, const int* __restrict__ pos)
{
    __shared__ __half As[2][128][40];
    __shared__ __half Ws[2][128][40];

    const int tid = threadIdx.x;
    const int m0 = blockIdx.y * 128;
    const int n0 = blockIdx.x * 128;
    const int w = tid >> 5, lane = tid & 31;
    const int wm = (w & 1) * 64;
    const int wn = (w >> 1) * 32;
    const int r = lane >> 2, c = lane & 3;
    const int l7 = lane & 7;

    // LDSM per-lane base offsets (bytes, within one buffer)
    const uint32_t sA0 = smem_u32(&As[0][0][0]);
    const uint32_t sW0 = smem_u32(&Ws[0][0][0]);
    const uint32_t BUFSZ = 128 * 40 * 2;  // 10240 bytes
    // A: lanes 0-7: rows+0 k0 | 8-15: rows+8 k0 | 16-23: rows+0 k8 | 24-31: rows+8 k8
    const uint32_t a_off = (uint32_t)((wm + (lane & 15)) * 80 + ((lane & 16) ? 16 : 0));
    // B: lanes 0-7: cols+0 k0 | 8-15: cols+0 k8 | 16-23: cols+8 k0 | 24-31: cols+8 k8
    const uint32_t b_off = (uint32_t)((wn + l7 + ((lane & 16) ? 8 : 0)) * 80
                                      + ((lane & 8) ? 16 : 0));

    float acc[4][4][4];
#pragma unroll
    for (int mt = 0; mt < 4; mt++)
#pragma unroll
        for (int nt = 0; nt < 4; nt++)
#pragma unroll
            for (int i = 0; i < 4; i++) acc[mt][nt][i] = 0.f;

    auto load_stage = [&](int buf, int kt) {
        int k0 = kt * 32;
#pragma unroll
        for (int i = 0; i < 2; i++) {
            int idx = tid + i * 256;
            int row = idx >> 2;
            int ch = (idx & 3) * 8;
            cp16(&As[buf][row][ch], A + (size_t)(m0 + row) * DD + k0 + ch);
            cp16(&Ws[buf][row][ch], W + (size_t)(n0 + row) * DD + k0 + ch);
        }
    };

    load_stage(0, 0);
    asm volatile("cp.async.commit_group;");

    int buf = 0;
    const int KT = DD / 32;  // 32
    for (int kt = 0; kt < KT; kt++) {
        if (kt + 1 < KT) {
            load_stage(buf ^ 1, kt + 1);
            asm volatile("cp.async.commit_group;");
            asm volatile("cp.async.wait_group 1;");
        } else {
            asm volatile("cp.async.wait_group 0;");
        }
        __syncthreads();

        const uint32_t aBase = sA0 + buf * BUFSZ + a_off;
        const uint32_t bBase = sW0 + buf * BUFSZ + b_off;
#pragma unroll
        for (int kk = 0; kk < 2; kk++) {
            uint32_t af[4][4];
#pragma unroll
            for (int mt = 0; mt < 4; mt++)
                ldsm_x4(af[mt][0], af[mt][1], af[mt][2], af[mt][3],
                        aBase + mt * (16 * 80) + kk * 32);
            uint32_t bf[4][2];
#pragma unroll
            for (int ntp = 0; ntp < 2; ntp++)
                ldsm_x4(bf[2*ntp][0], bf[2*ntp][1], bf[2*ntp+1][0], bf[2*ntp+1][1],
                        bBase + ntp * (16 * 80) + kk * 32);
#pragma unroll
            for (int mt = 0; mt < 4; mt++)
#pragma unroll
                for (int nt = 0; nt < 4; nt++)
                    mma_f16(acc[mt][nt], af[mt], bf[nt][0], bf[nt][1]);
        }
        __syncthreads();
        buf ^= 1;
    }

    // ---------------- epilogue ----------------
    const float LN_TH_OVER = 9.210340372f / 64.0f;  // ln(10000)/64
#pragma unroll
    for (int mt = 0; mt < 4; mt++) {
#pragma unroll
        for (int nt = 0; nt < 4; nt++) {
            int n = n0 + wn + nt * 8 + c * 2;       // even column
#pragma unroll
            for (int half = 0; half < 2; half++) {
                int m = m0 + wm + mt * 16 + r + half * 8;
                float v0 = acc[mt][nt][half * 2];
                float v1 = acc[mt][nt][half * 2 + 1];
                if (EPI == 0) {
                    *(float2*)(Cout + (size_t)m * DD + n) = make_float2(v0, v1);
                } else if (EPI == 3) {
                    int b = m >> 11, s = m & (SS - 1);
                    int h = n >> 6, dk = n & 63;
                    __half* dst = g_Vt + ((size_t)(b * HH + h) * DKK + dk) * SS + s;
                    dst[0]  = __float2half_rn(v0);
                    dst[SS] = __float2half_rn(v1);
                } else {
                    int b = m >> 11, s = m & (SS - 1);
                    int h = n >> 6, dk = n & 63;  // even
                    float p = (float)pos[s];
                    float inv = expf(-(float)dk * LN_TH_OVER);
                    float sn, cs;
                    sincosf(p * inv, &sn, &cs);
                    float o0 = v0 * cs - v1 * sn;
                    float o1 = v0 * sn + v1 * cs;
                    if (EPI == 1) { o0 *= 0.125f; o1 *= 0.125f; }
                    __half* dst = (EPI == 1 ? g_Qh : g_Kh)
                               + (((size_t)(b * HH + h) * SS + s) * DKK + dk);
                    *(uint32_t*)dst = packh2(o0, o1);
                }
            }
        }
    }
}

// ---------------------------------------------------------------------------
// FlashAttention-2 style fp16 tensor-core attention with LDSM fragment loads.
// Block: 128 Q rows, 8 warps (16 rows each). KV tile 64. Causal.
// K smem: [kv][d] 128B rows; V smem: [d][kv] 128B rows; XOR-16B swizzle.
// ---------------------------------------------------------------------------
__global__ __launch_bounds__(256, 2)
void attn_kernel()
{
    __shared__ __align__(16) char sK[2][64 * 128];
    __shared__ __align__(16) char sV[2][64 * 128];

    const int qt = (int)gridDim.x - 1 - (int)blockIdx.x;  // heavy tiles first
    const int h  = blockIdx.y;
    const int b  = blockIdx.z;
    const int tid = threadIdx.x;
    const int w = tid >> 5, lane = tid & 31;
    const int g = lane >> 2, c = lane & 3;
    const int q0w = qt * 128 + w * 16;

    const __half* Qbh = g_Qh + (size_t)(b * HH + h) * SS * DKK;
    const __half* Kbh = g_Kh + (size_t)(b * HH + h) * SS * DKK;
    const __half* Vbh = g_Vt + (size_t)(b * HH + h) * DKK * SS;

    // LDSM per-lane constants: q-th 8-lane group addresses chunk q (then q+4)
    const int r7 = lane & 7, qg = lane >> 3;
    const uint32_t sK0 = smem_u32(&sK[0][0]);
    const uint32_t sV0 = smem_u32(&sV[0][0]);
    const uint32_t swz0 = (uint32_t)(((qg     ^ r7) << 4) + r7 * 128);
    const uint32_t swz1 = (uint32_t)((((qg+4) ^ r7) << 4) + r7 * 128);

    uint32_t qreg[4][4];
#pragma unroll
    for (int kk = 0; kk < 4; kk++) {
        qreg[kk][0] = *(const uint32_t*)(Qbh + (q0w + g) * DKK + 16 * kk + 2 * c);
        qreg[kk][1] = *(const uint32_t*)(Qbh + (q0w + g + 8) * DKK + 16 * kk + 2 * c);
        qreg[kk][2] = *(const uint32_t*)(Qbh + (q0w + g) * DKK + 16 * kk + 2 * c + 8);
        qreg[kk][3] = *(const uint32_t*)(Qbh + (q0w + g + 8) * DKK + 16 * kk + 2 * c + 8);
    }

    float Oc[8][4];
#pragma unroll
    for (int n = 0; n < 8; n++)
#pragma unroll
        for (int i = 0; i < 4; i++) Oc[n][i] = 0.f;
    float mrow[2] = {-1e30f, -1e30f};
    float lrow[2] = {0.f, 0.f};

    auto load_kv = [&](int bufi, int kt) {
        int kv0 = kt * 64;
#pragma unroll
        for (int i = 0; i < 2; i++) {
            int idx = tid + i * 256;
            int r = idx >> 3;
            int ch = idx & 7;
            int dst = r * 128 + ((ch ^ (r & 7)) << 4);
            cp16(sK[bufi] + dst, Kbh + (size_t)(kv0 + r) * DKK + ch * 8);
            cp16(sV[bufi] + dst, Vbh + (size_t)r * SS + kv0 + ch * 8);
        }
    };

    const int ktmax = qt * 2 + 1;
    load_kv(0, 0);
    asm volatile("cp.async.commit_group;");

    int buf = 0;
    for (int kt = 0; kt <= ktmax; kt++) {
        if (kt < ktmax) {
            load_kv(buf ^ 1, kt + 1);
            asm volatile("cp.async.commit_group;");
            asm volatile("cp.async.wait_group 1;");
        } else {
            asm volatile("cp.async.wait_group 0;");
        }
        __syncthreads();

        const int kv0 = kt * 64;
        const uint32_t kb0 = sK0 + buf * 8192 + swz0;
        const uint32_t kb1 = sK0 + buf * 8192 + swz1;

        float Sc[8][4];
#pragma unroll
        for (int n = 0; n < 8; n++)
#pragma unroll
            for (int i = 0; i < 4; i++) Sc[n][i] = 0.f;

#pragma unroll
        for (int n = 0; n < 8; n++) {
            uint32_t b00, b01, b10, b11, b20, b21, b30, b31;
            ldsm_x4(b00, b01, b10, b11, kb0 + n * 1024);
            ldsm_x4(b20, b21, b30, b31, kb1 + n * 1024);
            mma_f16(Sc[n], qreg[0], b00, b01);
            mma_f16(Sc[n], qreg[1], b10, b11);
            mma_f16(Sc[n], qreg[2], b20, b21);
            mma_f16(Sc[n], qreg[3], b30, b31);
        }

        if (kv0 + 63 > q0w) {
            int r0 = q0w + g, r1 = q0w + g + 8;
#pragma unroll
            for (int n = 0; n < 8; n++) {
                int col = kv0 + n * 8 + 2 * c;
                if (col > r0)     Sc[n][0] = -1e30f;
                if (col + 1 > r0) Sc[n][1] = -1e30f;
                if (col > r1)     Sc[n][2] = -1e30f;
                if (col + 1 > r1) Sc[n][3] = -1e30f;
            }
        }

        float mx0 = Sc[0][0], mx1 = Sc[0][2];
#pragma unroll
        for (int n = 0; n < 8; n++) {
            mx0 = fmaxf(mx0, fmaxf(Sc[n][0], Sc[n][1]));
            mx1 = fmaxf(mx1, fmaxf(Sc[n][2], Sc[n][3]));
        }
        mx0 = fmaxf(mx0, __shfl_xor_sync(0xffffffffu, mx0, 1));
        mx0 = fmaxf(mx0, __shfl_xor_sync(0xffffffffu, mx0, 2));
        mx1 = fmaxf(mx1, __shfl_xor_sync(0xffffffffu, mx1, 1));
        mx1 = fmaxf(mx1, __shfl_xor_sync(0xffffffffu, mx1, 2));

        float mn0 = fmaxf(mrow[0], mx0);
        float mn1 = fmaxf(mrow[1], mx1);
        float a0 = __expf(mrow[0] - mn0);
        float a1 = __expf(mrow[1] - mn1);

        float rs0 = 0.f, rs1 = 0.f;
#pragma unroll
        for (int n = 0; n < 8; n++) {
            Sc[n][0] = __expf(Sc[n][0] - mn0);
            Sc[n][1] = __expf(Sc[n][1] - mn0);
            Sc[n][2] = __expf(Sc[n][2] - mn1);
            Sc[n][3] = __expf(Sc[n][3] - mn1);
            rs0 += Sc[n][0] + Sc[n][1];
            rs1 += Sc[n][2] + Sc[n][3];
        }
        rs0 += __shfl_xor_sync(0xffffffffu, rs0, 1);
        rs0 += __shfl_xor_sync(0xffffffffu, rs0, 2);
        rs1 += __shfl_xor_sync(0xffffffffu, rs1, 1);
        rs1 += __shfl_xor_sync(0xffffffffu, rs1, 2);

        lrow[0] = lrow[0] * a0 + rs0;
        lrow[1] = lrow[1] * a1 + rs1;
        mrow[0] = mn0; mrow[1] = mn1;

#pragma unroll
        for (int n = 0; n < 8; n++) {
            Oc[n][0] *= a0; Oc[n][1] *= a0;
            Oc[n][2] *= a1; Oc[n][3] *= a1;
        }

        uint32_t pa[4][4];
#pragma unroll
        for (int kk = 0; kk < 4; kk++) {
            pa[kk][0] = packh2(Sc[2 * kk][0],     Sc[2 * kk][1]);
            pa[kk][1] = packh2(Sc[2 * kk][2],     Sc[2 * kk][3]);
            pa[kk][2] = packh2(Sc[2 * kk + 1][0], Sc[2 * kk + 1][1]);
            pa[kk][3] = packh2(Sc[2 * kk + 1][2], Sc[2 * kk + 1][3]);
        }

        const uint32_t vb0 = sV0 + buf * 8192 + swz0;
        const uint32_t vb1 = sV0 + buf * 8192 + swz1;
#pragma unroll
        for (int nd = 0; nd < 8; nd++) {
            uint32_t b00, b01, b10, b11, b20, b21, b30, b31;
            ldsm_x4(b00, b01, b10, b11, vb0 + nd * 1024);
            ldsm_x4(b20, b21, b30, b31, vb1 + nd * 1024);
            mma_f16(Oc[nd], pa[0], b00, b01);
            mma_f16(Oc[nd], pa[1], b10, b11);
            mma_f16(Oc[nd], pa[2], b20, b21);
            mma_f16(Oc[nd], pa[3], b30, b31);
        }

        __syncthreads();
        buf ^= 1;
    }

    float inv0 = 1.f / lrow[0];
    float inv1 = 1.f / lrow[1];
    __half* Cb0 = g_Ctxh + ((size_t)(b * SS + q0w + g) * DD + h * 64);
    __half* Cb1 = g_Ctxh + ((size_t)(b * SS + q0w + g + 8) * DD + h * 64);
#pragma unroll
    for (int nd = 0; nd < 8; nd++) {
        int col = nd * 8 + 2 * c;
        *(uint32_t*)(Cb0 + col) = packh2(Oc[nd][0] * inv0, Oc[nd][1] * inv0);
        *(uint32_t*)(Cb1 + col) = packh2(Oc[nd][2] * inv1, Oc[nd][3] * inv1);
    }
}

// ---------------------------------------------------------------------------
extern "C" void kernel_launch(void* const* d_in, const int* in_sizes, int n_in,
                              void* d_out, int out_size)
{
    const float* x  = (const float*)d_in[0];
    const float* Wq = (const float*)d_in[1];
    const float* Wk = (const float*)d_in[2];
    const float* Wv = (const float*)d_in[3];
    const float* Wo = (const float*)d_in[4];
    const int* pos  = (const int*)d_in[5];
    float* out = (float*)d_out;

    void* xh_ptr = nullptr, *wh_ptr = nullptr, *ctxh_ptr = nullptr;
    cudaGetSymbolAddress(&xh_ptr, g_xh);
    cudaGetSymbolAddress(&wh_ptr, g_Wh);
    cudaGetSymbolAddress(&ctxh_ptr, g_Ctxh);
    __half* xh = (__half*)xh_ptr;
    __half* wh = (__half*)wh_ptr;

    cvt_kernel<<<2048, 256>>>(x, xh, M_TOTAL * DD / 4);
    {
        dim3 cg(512, 1, 4);
        cvtw_kernel<<<cg, 256>>>(Wq, Wk, Wv, Wo, DD * DD / 4);
    }

    dim3 ggrid(DD / 128, M_TOTAL / 128);   // 8 x 64

    gemm_f16_kernel<1><<<ggrid, 256>>>(xh, wh + 0*DD*DD, nullptr, pos);
    gemm_f16_kernel<2><<<ggrid, 256>>>(xh, wh + 1*DD*DD, nullptr, pos);
    gemm_f16_kernel<3><<<ggrid, 256>>>(xh, wh + 2*DD*DD, nullptr, pos);

    dim3 agrid(SS / 128, HH, BB);
    attn_kernel<<<agrid, 256>>>();

    gemm_f16_kernel<0><<<ggrid, 256>>>((const __half*)ctxh_ptr, wh + 3*DD*DD,
                                       out, pos);
}

// round 8
// speedup vs baseline: 1.7576x; 1.0818x over previous
#include <cuda_runtime.h>
#include <cuda_fp16.h>
#include <math.h>
#include <stdint.h>

#define BB 4
#define SS 2048
#define DD 1024
#define HH 16
#define DKK 64
#define M_TOTAL (BB*SS)

// Scratch (device globals; allocation-free per harness rules)
__device__ __half g_xh [M_TOTAL*DD];     // fp16 copy of x
__device__ __half g_Wh [4*DD*DD];        // fp16 copies of Wq,Wk,Wv,Wo
__device__ __half g_Qh [BB*HH*SS*DKK];   // [b,h,s,d], pre-scaled by 1/8
__device__ __half g_Kh [BB*HH*SS*DKK];   // [b,h,s,d]
__device__ __half g_Vt [BB*HH*DKK*SS];   // [b,h,d,s]  (transposed V)
__device__ __half g_Ctxh[M_TOTAL*DD];    // fp16 context [b,s,D]

// ---------------------------------------------------------------------------
// helpers
// ---------------------------------------------------------------------------
__device__ __forceinline__ uint32_t smem_u32(const void* p) {
    uint32_t a;
    asm("{ .reg .u64 t; cvta.to.shared.u64 t, %1; cvt.u32.u64 %0, t; }"
        : "=r"(a) : "l"(p));
    return a;
}

__device__ __forceinline__ void mma_f16(float* c, const uint32_t* a,
                                        uint32_t b0, uint32_t b1) {
    asm volatile(
        "mma.sync.aligned.m16n8k16.row.col.f32.f16.f16.f32 "
        "{%0,%1,%2,%3},{%4,%5,%6,%7},{%8,%9},{%0,%1,%2,%3};"
        : "+f"(c[0]), "+f"(c[1]), "+f"(c[2]), "+f"(c[3])
        : "r"(a[0]), "r"(a[1]), "r"(a[2]), "r"(a[3]), "r"(b0), "r"(b1));
}

__device__ __forceinline__ void ldsm_x4(uint32_t& r0, uint32_t& r1,
                                        uint32_t& r2, uint32_t& r3, uint32_t addr) {
    asm volatile("ldmatrix.sync.aligned.m8n8.x4.shared.b16 {%0,%1,%2,%3}, [%4];"
                 : "=r"(r0), "=r"(r1), "=r"(r2), "=r"(r3) : "r"(addr));
}

__device__ __forceinline__ void cp16(void* smem, const void* g) {
    uint32_t s = smem_u32(smem);
    asm volatile("cp.async.cg.shared.global [%0], [%1], 16;" :: "r"(s), "l"(g));
}

__device__ __forceinline__ uint32_t packh2(float lo, float hi) {
    __half2 h = __floats2half2_rn(lo, hi);
    return *(uint32_t*)&h;
}

// ---------------------------------------------------------------------------
// fp32 -> fp16 conversions
// ---------------------------------------------------------------------------
__global__ void cvt_kernel(const float* __restrict__ src, __half* __restrict__ dst,
                           int n4)
{
    int i = blockIdx.x * blockDim.x + threadIdx.x;
    for (; i < n4; i += gridDim.x * blockDim.x) {
        float4 v = ((const float4*)src)[i];
        ((uint2*)dst)[i] = make_uint2(packh2(v.x, v.y), packh2(v.z, v.w));
    }
}

__global__ void cvtw_kernel(const float* W0, const float* W1,
                            const float* W2, const float* W3, int n4)
{
    const float* src = blockIdx.z == 0 ? W0 : blockIdx.z == 1 ? W1
                     : blockIdx.z == 2 ? W2 : W3;
    __half* dst = g_Wh + (size_t)blockIdx.z * DD * DD;
    int i = blockIdx.x * blockDim.x + threadIdx.x;
    for (; i < n4; i += gridDim.x * blockDim.x) {
        float4 v = ((const float4*)src)[i];
        ((uint2*)dst)[i] = make_uint2(packh2(v.x, v.y), packh2(v.z, v.w));
    }
}

// ---------------------------------------------------------------------------
// fp16 tensor-core GEMM (HMMA + LDSM), 3-stage cp.async pipeline.
// C[m,n] = sum_k A[m,k] * W[n,k].  Block tile 128x128, K-chunk 32.
// 8 warps: 2(M) x 4(N), warp tile 64x32 (4x4 m16n8k16, 2 k-steps/chunk).
// Dynamic smem: 3 stages x (A 10240B + W 10240B) = 61440B.
// MODE 0: QKV merged; blockIdx.z selects W and epilogue (0=Q rope*1/8,
//         1=K rope, 2=V transposed).  MODE 1: Wo, fp32 row-major out.
// ---------------------------------------------------------------------------
#define STAGE_BYTES 20480
#define GSMEM_TOTAL (3 * STAGE_BYTES)

template<int MODE>
__global__ __launch_bounds__(256)
void gemm3_kernel(const __half* __restrict__ A, float* __restrict__ Cout,
                  const int* __restrict__ pos)
{
    extern __shared__ char dsm[];
    const int z = (MODE == 0) ? blockIdx.z : 3;
    const __half* __restrict__ W = g_Wh + (size_t)z * DD * DD;

    const int tid = threadIdx.x;
    const int m0 = blockIdx.y * 128;
    const int n0 = blockIdx.x * 128;
    const int w = tid >> 5, lane = tid & 31;
    const int wm = (w & 1) * 64;
    const int wn = (w >> 1) * 32;
    const int r = lane >> 2, c = lane & 3;
    const int l7 = lane & 7;

    const uint32_t sbase = smem_u32(dsm);
    // A: lanes 0-7: rows+0 k0 | 8-15: rows+8 k0 | 16-23: rows+0 k8 | 24-31: rows+8 k8
    const uint32_t a_off = (uint32_t)((wm + (lane & 15)) * 80 + ((lane & 16) ? 16 : 0));
    // B: lanes 0-7: cols+0 k0 | 8-15: cols+0 k8 | 16-23: cols+8 k0 | 24-31: cols+8 k8
    const uint32_t b_off = (uint32_t)(10240 + (wn + l7 + ((lane & 16) ? 8 : 0)) * 80
                                      + ((lane & 8) ? 16 : 0));

    float acc[4][4][4];
#pragma unroll
    for (int mt = 0; mt < 4; mt++)
#pragma unroll
        for (int nt = 0; nt < 4; nt++)
#pragma unroll
            for (int i = 0; i < 4; i++) acc[mt][nt][i] = 0.f;

    auto load_stage = [&](int st, int kt) {
        int k0 = kt * 32;
        char* sA = dsm + st * STAGE_BYTES;
        char* sW = sA + 10240;
#pragma unroll
        for (int i = 0; i < 2; i++) {
            int idx = tid + i * 256;
            int row = idx >> 2;
            int ch = (idx & 3) * 8;
            cp16(sA + row * 80 + ch * 2, A + (size_t)(m0 + row) * DD + k0 + ch);
            cp16(sW + row * 80 + ch * 2, W + (size_t)(n0 + row) * DD + k0 + ch);
        }
        asm volatile("cp.async.commit_group;");
    };

    const int KT = DD / 32;  // 32
    load_stage(0, 0);
    load_stage(1, 1);

    int st = 0;
    for (int kt = 0; kt < KT; kt++) {
        if (kt + 1 < KT) asm volatile("cp.async.wait_group 1;");
        else             asm volatile("cp.async.wait_group 0;");
        __syncthreads();   // stage kt visible; all warps done with stage kt-1

        if (kt + 2 < KT) {
            int nst = st + 2; if (nst >= 3) nst -= 3;
            load_stage(nst, kt + 2);
        }

        const uint32_t aBase = sbase + st * STAGE_BYTES + a_off;
        const uint32_t bBase = sbase + st * STAGE_BYTES + b_off;
#pragma unroll
        for (int kk = 0; kk < 2; kk++) {
            uint32_t af[4][4];
#pragma unroll
            for (int mt = 0; mt < 4; mt++)
                ldsm_x4(af[mt][0], af[mt][1], af[mt][2], af[mt][3],
                        aBase + mt * (16 * 80) + kk * 32);
            uint32_t bf[4][2];
#pragma unroll
            for (int ntp = 0; ntp < 2; ntp++)
                ldsm_x4(bf[2*ntp][0], bf[2*ntp][1], bf[2*ntp+1][0], bf[2*ntp+1][1],
                        bBase + ntp * (16 * 80) + kk * 32);
#pragma unroll
            for (int mt = 0; mt < 4; mt++)
#pragma unroll
                for (int nt = 0; nt < 4; nt++)
                    mma_f16(acc[mt][nt], af[mt], bf[nt][0], bf[nt][1]);
        }
        st++; if (st >= 3) st -= 3;
    }

    // ---------------- epilogue ----------------
    const float LN_TH_OVER = 9.210340372f / 64.0f;  // ln(10000)/64
#pragma unroll
    for (int mt = 0; mt < 4; mt++) {
#pragma unroll
        for (int nt = 0; nt < 4; nt++) {
            int n = n0 + wn + nt * 8 + c * 2;       // even column
#pragma unroll
            for (int half = 0; half < 2; half++) {
                int m = m0 + wm + mt * 16 + r + half * 8;
                float v0 = acc[mt][nt][half * 2];
                float v1 = acc[mt][nt][half * 2 + 1];
                if (MODE == 1) {
                    *(float2*)(Cout + (size_t)m * DD + n) = make_float2(v0, v1);
                } else if (z == 2) {
                    int b = m >> 11, s = m & (SS - 1);
                    int h = n >> 6, dk = n & 63;
                    __half* dst = g_Vt + ((size_t)(b * HH + h) * DKK + dk) * SS + s;
                    dst[0]  = __float2half_rn(v0);
                    dst[SS] = __float2half_rn(v1);
                } else {
                    int b = m >> 11, s = m & (SS - 1);
                    int h = n >> 6, dk = n & 63;  // even
                    float p = (float)pos[s];
                    float inv = expf(-(float)dk * LN_TH_OVER);
                    float sn, cs;
                    sincosf(p * inv, &sn, &cs);
                    float o0 = v0 * cs - v1 * sn;
                    float o1 = v0 * sn + v1 * cs;
                    if (z == 0) { o0 *= 0.125f; o1 *= 0.125f; }
                    __half* dst = (z == 0 ? g_Qh : g_Kh)
                               + (((size_t)(b * HH + h) * SS + s) * DKK + dk);
                    *(uint32_t*)dst = packh2(o0, o1);
                }
            }
        }
    }
}

// ---------------------------------------------------------------------------
// FlashAttention-2 style fp16 tensor-core attention with LDSM (unchanged R7).
// ---------------------------------------------------------------------------
__global__ __launch_bounds__(256, 2)
void attn_kernel()
{
    __shared__ __align__(16) char sK[2][64 * 128];
    __shared__ __align__(16) char sV[2][64 * 128];

    const int qt = (int)gridDim.x - 1 - (int)blockIdx.x;  // heavy tiles first
    const int h  = blockIdx.y;
    const int b  = blockIdx.z;
    const int tid = threadIdx.x;
    const int w = tid >> 5, lane = tid & 31;
    const int g = lane >> 2, c = lane & 3;
    const int q0w = qt * 128 + w * 16;

    const __half* Qbh = g_Qh + (size_t)(b * HH + h) * SS * DKK;
    const __half* Kbh = g_Kh + (size_t)(b * HH + h) * SS * DKK;
    const __half* Vbh = g_Vt + (size_t)(b * HH + h) * DKK * SS;

    const int r7 = lane & 7, qg = lane >> 3;
    const uint32_t sK0 = smem_u32(&sK[0][0]);
    const uint32_t sV0 = smem_u32(&sV[0][0]);
    const uint32_t swz0 = (uint32_t)(((qg     ^ r7) << 4) + r7 * 128);
    const uint32_t swz1 = (uint32_t)((((qg+4) ^ r7) << 4) + r7 * 128);

    uint32_t qreg[4][4];
#pragma unroll
    for (int kk = 0; kk < 4; kk++) {
        qreg[kk][0] = *(const uint32_t*)(Qbh + (q0w + g) * DKK + 16 * kk + 2 * c);
        qreg[kk][1] = *(const uint32_t*)(Qbh + (q0w + g + 8) * DKK + 16 * kk + 2 * c);
        qreg[kk][2] = *(const uint32_t*)(Qbh + (q0w + g) * DKK + 16 * kk + 2 * c + 8);
        qreg[kk][3] = *(const uint32_t*)(Qbh + (q0w + g + 8) * DKK + 16 * kk + 2 * c + 8);
    }

    float Oc[8][4];
#pragma unroll
    for (int n = 0; n < 8; n++)
#pragma unroll
        for (int i = 0; i < 4; i++) Oc[n][i] = 0.f;
    float mrow[2] = {-1e30f, -1e30f};
    float lrow[2] = {0.f, 0.f};

    auto load_kv = [&](int bufi, int kt) {
        int kv0 = kt * 64;
#pragma unroll
        for (int i = 0; i < 2; i++) {
            int idx = tid + i * 256;
            int r = idx >> 3;
            int ch = idx & 7;
            int dst = r * 128 + ((ch ^ (r & 7)) << 4);
            cp16(sK[bufi] + dst, Kbh + (size_t)(kv0 + r) * DKK + ch * 8);
            cp16(sV[bufi] + dst, Vbh + (size_t)r * SS + kv0 + ch * 8);
        }
    };

    const int ktmax = qt * 2 + 1;
    load_kv(0, 0);
    asm volatile("cp.async.commit_group;");

    int buf = 0;
    for (int kt = 0; kt <= ktmax; kt++) {
        if (kt < ktmax) {
            load_kv(buf ^ 1, kt + 1);
            asm volatile("cp.async.commit_group;");
            asm volatile("cp.async.wait_group 1;");
        } else {
            asm volatile("cp.async.wait_group 0;");
        }
        __syncthreads();

        const int kv0 = kt * 64;
        const uint32_t kb0 = sK0 + buf * 8192 + swz0;
        const uint32_t kb1 = sK0 + buf * 8192 + swz1;

        float Sc[8][4];
#pragma unroll
        for (int n = 0; n < 8; n++)
#pragma unroll
            for (int i = 0; i < 4; i++) Sc[n][i] = 0.f;

#pragma unroll
        for (int n = 0; n < 8; n++) {
            uint32_t b00, b01, b10, b11, b20, b21, b30, b31;
            ldsm_x4(b00, b01, b10, b11, kb0 + n * 1024);
            ldsm_x4(b20, b21, b30, b31, kb1 + n * 1024);
            mma_f16(Sc[n], qreg[0], b00, b01);
            mma_f16(Sc[n], qreg[1], b10, b11);
            mma_f16(Sc[n], qreg[2], b20, b21);
            mma_f16(Sc[n], qreg[3], b30, b31);
        }

        if (kv0 + 63 > q0w) {
            int r0 = q0w + g, r1 = q0w + g + 8;
#pragma unroll
            for (int n = 0; n < 8; n++) {
                int col = kv0 + n * 8 + 2 * c;
                if (col > r0)     Sc[n][0] = -1e30f;
                if (col + 1 > r0) Sc[n][1] = -1e30f;
                if (col > r1)     Sc[n][2] = -1e30f;
                if (col + 1 > r1) Sc[n][3] = -1e30f;
            }
        }

        float mx0 = Sc[0][0], mx1 = Sc[0][2];
#pragma unroll
        for (int n = 0; n < 8; n++) {
            mx0 = fmaxf(mx0, fmaxf(Sc[n][0], Sc[n][1]));
            mx1 = fmaxf(mx1, fmaxf(Sc[n][2], Sc[n][3]));
        }
        mx0 = fmaxf(mx0, __shfl_xor_sync(0xffffffffu, mx0, 1));
        mx0 = fmaxf(mx0, __shfl_xor_sync(0xffffffffu, mx0, 2));
        mx1 = fmaxf(mx1, __shfl_xor_sync(0xffffffffu, mx1, 1));
        mx1 = fmaxf(mx1, __shfl_xor_sync(0xffffffffu, mx1, 2));

        float mn0 = fmaxf(mrow[0], mx0);
        float mn1 = fmaxf(mrow[1], mx1);
        float a0 = __expf(mrow[0] - mn0);
        float a1 = __expf(mrow[1] - mn1);

        float rs0 = 0.f, rs1 = 0.f;
#pragma unroll
        for (int n = 0; n < 8; n++) {
            Sc[n][0] = __expf(Sc[n][0] - mn0);
            Sc[n][1] = __expf(Sc[n][1] - mn0);
            Sc[n][2] = __expf(Sc[n][2] - mn1);
            Sc[n][3] = __expf(Sc[n][3] - mn1);
            rs0 += Sc[n][0] + Sc[n][1];
            rs1 += Sc[n][2] + Sc[n][3];
        }
        rs0 += __shfl_xor_sync(0xffffffffu, rs0, 1);
        rs0 += __shfl_xor_sync(0xffffffffu, rs0, 2);
        rs1 += __shfl_xor_sync(0xffffffffu, rs1, 1);
        rs1 += __shfl_xor_sync(0xffffffffu, rs1, 2);

        lrow[0] = lrow[0] * a0 + rs0;
        lrow[1] = lrow[1] * a1 + rs1;
        mrow[0] = mn0; mrow[1] = mn1;

#pragma unroll
        for (int n = 0; n < 8; n++) {
            Oc[n][0] *= a0; Oc[n][1] *= a0;
            Oc[n][2] *= a1; Oc[n][3] *= a1;
        }

        uint32_t pa[4][4];
#pragma unroll
        for (int kk = 0; kk < 4; kk++) {
            pa[kk][0] = packh2(Sc[2 * kk][0],     Sc[2 * kk][1]);
            pa[kk][1] = packh2(Sc[2 * kk][2],     Sc[2 * kk][3]);
            pa[kk][2] = packh2(Sc[2 * kk + 1][0], Sc[2 * kk + 1][1]);
            pa[kk][3] = packh2(Sc[2 * kk + 1][2], Sc[2 * kk + 1][3]);
        }

        const uint32_t vb0 = sV0 + buf * 8192 + swz0;
        const uint32_t vb1 = sV0 + buf * 8192 + swz1;
#pragma unroll
        for (int nd = 0; nd < 8; nd++) {
            uint32_t b00, b01, b10, b11, b20, b21, b30, b31;
            ldsm_x4(b00, b01, b10, b11, vb0 + nd * 1024);
            ldsm_x4(b20, b21, b30, b31, vb1 + nd * 1024);
            mma_f16(Oc[nd], pa[0], b00, b01);
            mma_f16(Oc[nd], pa[1], b10, b11);
            mma_f16(Oc[nd], pa[2], b20, b21);
            mma_f16(Oc[nd], pa[3], b30, b31);
        }

        __syncthreads();
        buf ^= 1;
    }

    float inv0 = 1.f / lrow[0];
    float inv1 = 1.f / lrow[1];
    __half* Cb0 = g_Ctxh + ((size_t)(b * SS + q0w + g) * DD + h * 64);
    __half* Cb1 = g_Ctxh + ((size_t)(b * SS + q0w + g + 8) * DD + h * 64);
#pragma unroll
    for (int nd = 0; nd < 8; nd++) {
        int col = nd * 8 + 2 * c;
        *(uint32_t*)(Cb0 + col) = packh2(Oc[nd][0] * inv0, Oc[nd][1] * inv0);
        *(uint32_t*)(Cb1 + col) = packh2(Oc[nd][2] * inv1, Oc[nd][3] * inv1);
    }
}

// ---------------------------------------------------------------------------
extern "C" void kernel_launch(void* const* d_in, const int* in_sizes, int n_in,
                              void* d_out, int out_size)
{
    const float* x  = (const float*)d_in[0];
    const float* Wq = (const float*)d_in[1];
    const float* Wk = (const float*)d_in[2];
    const float* Wv = (const float*)d_in[3];
    const float* Wo = (const float*)d_in[4];
    const int* pos  = (const int*)d_in[5];
    float* out = (float*)d_out;

    void* xh_ptr = nullptr, *ctxh_ptr = nullptr;
    cudaGetSymbolAddress(&xh_ptr, g_xh);
    cudaGetSymbolAddress(&ctxh_ptr, g_Ctxh);
    __half* xh = (__half*)xh_ptr;

    static int attr_set = 0;
    if (!attr_set) {
        cudaFuncSetAttribute(gemm3_kernel<0>,
                             cudaFuncAttributeMaxDynamicSharedMemorySize, GSMEM_TOTAL);
        cudaFuncSetAttribute(gemm3_kernel<1>,
                             cudaFuncAttributeMaxDynamicSharedMemorySize, GSMEM_TOTAL);
        attr_set = 1;
    }

    cvt_kernel<<<2048, 256>>>(x, xh, M_TOTAL * DD / 4);
    {
        dim3 cg(512, 1, 4);
        cvtw_kernel<<<cg, 256>>>(Wq, Wk, Wv, Wo, DD * DD / 4);
    }

    dim3 gq(DD / 128, M_TOTAL / 128, 3);   // 8 x 64 x 3
    gemm3_kernel<0><<<gq, 256, GSMEM_TOTAL>>>(xh, nullptr, pos);

    dim3 agrid(SS / 128, HH, BB);
    attn_kernel<<<agrid, 256>>>();

    dim3 go(DD / 128, M_TOTAL / 128);      // 8 x 64
    gemm3_kernel<1><<<go, 256, GSMEM_TOTAL>>>((const __half*)ctxh_ptr, out, pos);
}

// round 9
// speedup vs baseline: 1.9151x; 1.0896x over previous
#include <cuda_runtime.h>
#include <cuda_fp16.h>
#include <math.h>
#include <stdint.h>

#define BB 4
#define SS 2048
#define DD 1024
#define HH 16
#define DKK 64
#define M_TOTAL (BB*SS)

// Scratch (device globals; allocation-free per harness rules)
__device__ __half g_xh [M_TOTAL*DD];     // fp16 copy of x
__device__ __half g_Wh [4*DD*DD];        // fp16 copies of Wq,Wk,Wv,Wo
__device__ __half g_Qh [BB*HH*SS*DKK];   // [b,h,s,d], pre-scaled by log2e/8
__device__ __half g_Kh [BB*HH*SS*DKK];   // [b,h,s,d]
__device__ __half g_Vt [BB*HH*DKK*SS];   // [b,h,d,s]  (transposed V)
__device__ __half g_Ctxh[M_TOTAL*DD];    // fp16 context [b,s,D]

// ---------------------------------------------------------------------------
// helpers
// ---------------------------------------------------------------------------
__device__ __forceinline__ uint32_t smem_u32(const void* p) {
    uint32_t a;
    asm("{ .reg .u64 t; cvta.to.shared.u64 t, %1; cvt.u32.u64 %0, t; }"
        : "=r"(a) : "l"(p));
    return a;
}

__device__ __forceinline__ void mma_f16(float* c, const uint32_t* a,
                                        uint32_t b0, uint32_t b1) {
    asm volatile(
        "mma.sync.aligned.m16n8k16.row.col.f32.f16.f16.f32 "
        "{%0,%1,%2,%3},{%4,%5,%6,%7},{%8,%9},{%0,%1,%2,%3};"
        : "+f"(c[0]), "+f"(c[1]), "+f"(c[2]), "+f"(c[3])
        : "r"(a[0]), "r"(a[1]), "r"(a[2]), "r"(a[3]), "r"(b0), "r"(b1));
}

__device__ __forceinline__ void ldsm_x4(uint32_t& r0, uint32_t& r1,
                                        uint32_t& r2, uint32_t& r3, uint32_t addr) {
    asm volatile("ldmatrix.sync.aligned.m8n8.x4.shared.b16 {%0,%1,%2,%3}, [%4];"
                 : "=r"(r0), "=r"(r1), "=r"(r2), "=r"(r3) : "r"(addr));
}

__device__ __forceinline__ void cp16(void* smem, const void* g) {
    uint32_t s = smem_u32(smem);
    asm volatile("cp.async.cg.shared.global [%0], [%1], 16;" :: "r"(s), "l"(g));
}

__device__ __forceinline__ uint32_t packh2(float lo, float hi) {
    __half2 h = __floats2half2_rn(lo, hi);
    return *(uint32_t*)&h;
}

// ---------------------------------------------------------------------------
// fp32 -> fp16 conversions
// ---------------------------------------------------------------------------
__global__ void cvt_kernel(const float* __restrict__ src, __half* __restrict__ dst,
                           int n4)
{
    int i = blockIdx.x * blockDim.x + threadIdx.x;
    for (; i < n4; i += gridDim.x * blockDim.x) {
        float4 v = ((const float4*)src)[i];
        ((uint2*)dst)[i] = make_uint2(packh2(v.x, v.y), packh2(v.z, v.w));
    }
}

__global__ void cvtw_kernel(const float* W0, const float* W1,
                            const float* W2, const float* W3, int n4)
{
    const float* src = blockIdx.z == 0 ? W0 : blockIdx.z == 1 ? W1
                     : blockIdx.z == 2 ? W2 : W3;
    __half* dst = g_Wh + (size_t)blockIdx.z * DD * DD;
    int i = blockIdx.x * blockDim.x + threadIdx.x;
    for (; i < n4; i += gridDim.x * blockDim.x) {
        float4 v = ((const float4*)src)[i];
        ((uint2*)dst)[i] = make_uint2(packh2(v.x, v.y), packh2(v.z, v.w));
    }
}

// ---------------------------------------------------------------------------
// fp16 tensor-core GEMM (HMMA + LDSM), 3-stage cp.async pipeline, K-chunk 64.
// C[m,n] = sum_k A[m,k] * W[n,k].  Block tile 128x128.
// 8 warps: 2(M) x 4(N), warp tile 64x32 (4 mt x 4 nt m16n8k16, 4 k-steps/chunk).
// Smem rows 72 halfs (144B pitch) -> LDSM conflict-free, additive offsets.
// Stage = A(128x144B=18432) + B(18432) = 36864B; 3 stages = 110592B dynamic.
// MODE 0: QKV merged; blockIdx.z selects W and epilogue (0=Q rope*log2e/8,
//         1=K rope, 2=V transposed).  MODE 1: Wo, fp32 row-major out.
// ---------------------------------------------------------------------------
#define PITCHB 144
#define A_BYTES (128 * PITCHB)
#define STAGE_BYTES (2 * A_BYTES)
#define GSMEM_TOTAL (3 * STAGE_BYTES)

template<int MODE>
__global__ __launch_bounds__(256)
void gemm3_kernel(const __half* __restrict__ A, float* __restrict__ Cout,
                  const int* __restrict__ pos)
{
    extern __shared__ char dsm[];
    const int z = (MODE == 0) ? blockIdx.z : 3;
    const __half* __restrict__ W = g_Wh + (size_t)z * DD * DD;

    const int tid = threadIdx.x;
    const int m0 = blockIdx.y * 128;
    const int n0 = blockIdx.x * 128;
    const int w = tid >> 5, lane = tid & 31;
    const int wm = (w & 1) * 64;
    const int wn = (w >> 1) * 32;
    const int r = lane >> 2, c = lane & 3;
    const int l7 = lane & 7;

    const uint32_t sbase = smem_u32(dsm);
    // A: lanes 0-7 rows+0,k0 | 8-15 rows+8,k0 | 16-23 rows+0,k8 | 24-31 rows+8,k8
    const uint32_t a_off = (uint32_t)((wm + (lane & 15)) * PITCHB
                                      + ((lane & 16) ? 16 : 0));
    // B: lanes 0-7 cols+0,k0 | 8-15 cols+0,k8 | 16-23 cols+8,k0 | 24-31 cols+8,k8
    const uint32_t b_off = (uint32_t)(A_BYTES
                                      + (wn + l7 + ((lane & 16) ? 8 : 0)) * PITCHB
                                      + ((lane & 8) ? 16 : 0));

    float acc[4][4][4];
#pragma unroll
    for (int mt = 0; mt < 4; mt++)
#pragma unroll
        for (int nt = 0; nt < 4; nt++)
#pragma unroll
            for (int i = 0; i < 4; i++) acc[mt][nt][i] = 0.f;

    // stage: 128 rows x 64 halfs (8x16B) for A and for B -> 8 cp16/thread
    auto load_stage = [&](int st, int kt) {
        int k0 = kt * 64;
        char* sA = dsm + st * STAGE_BYTES;
        char* sB = sA + A_BYTES;
#pragma unroll
        for (int i = 0; i < 4; i++) {
            int idx = tid + i * 256;       // 0..1023
            int row = idx >> 3;            // 0..127
            int ch = idx & 7;              // 16B chunk
            cp16(sA + row * PITCHB + ch * 16, A + (size_t)(m0 + row) * DD + k0 + ch * 8);
            cp16(sB + row * PITCHB + ch * 16, W + (size_t)(n0 + row) * DD + k0 + ch * 8);
        }
        asm volatile("cp.async.commit_group;");
    };

    const int KT = DD / 64;  // 16
    load_stage(0, 0);
    load_stage(1, 1);

    int st = 0;
    for (int kt = 0; kt < KT; kt++) {
        if (kt + 1 < KT) asm volatile("cp.async.wait_group 1;");
        else             asm volatile("cp.async.wait_group 0;");
        __syncthreads();   // stage kt visible; all warps done with stage kt-1

        if (kt + 2 < KT) {
            int nst = st + 2; if (nst >= 3) nst -= 3;
            load_stage(nst, kt + 2);   // overwrites slot of kt-1 (safe post-sync)
        }

        const uint32_t aBase = sbase + st * STAGE_BYTES + a_off;
        const uint32_t bBase = sbase + st * STAGE_BYTES + b_off;
#pragma unroll
        for (int kk = 0; kk < 4; kk++) {
            uint32_t af[4][4];
#pragma unroll
            for (int mt = 0; mt < 4; mt++)
                ldsm_x4(af[mt][0], af[mt][1], af[mt][2], af[mt][3],
                        aBase + mt * (16 * PITCHB) + kk * 32);
            uint32_t bf[4][2];
#pragma unroll
            for (int ntp = 0; ntp < 2; ntp++)
                ldsm_x4(bf[2*ntp][0], bf[2*ntp][1], bf[2*ntp+1][0], bf[2*ntp+1][1],
                        bBase + ntp * (16 * PITCHB) + kk * 32);
#pragma unroll
            for (int mt = 0; mt < 4; mt++)
#pragma unroll
                for (int nt = 0; nt < 4; nt++)
                    mma_f16(acc[mt][nt], af[mt], bf[nt][0], bf[nt][1]);
        }
        st++; if (st >= 3) st -= 3;
    }

    // ---------------- epilogue ----------------
    const float LN_TH_OVER = 9.210340372f / 64.0f;  // ln(10000)/64
    const float QSCALE = 0.125f * 1.44269504089f;   // fold log2e for exp2 softmax
#pragma unroll
    for (int mt = 0; mt < 4; mt++) {
#pragma unroll
        for (int nt = 0; nt < 4; nt++) {
            int n = n0 + wn + nt * 8 + c * 2;       // even column
#pragma unroll
            for (int half = 0; half < 2; half++) {
                int m = m0 + wm + mt * 16 + r + half * 8;
                float v0 = acc[mt][nt][half * 2];
                float v1 = acc[mt][nt][half * 2 + 1];
                if (MODE == 1) {
                    *(float2*)(Cout + (size_t)m * DD + n) = make_float2(v0, v1);
                } else if (z == 2) {
                    int b = m >> 11, s = m & (SS - 1);
                    int h = n >> 6, dk = n & 63;
                    __half* dst = g_Vt + ((size_t)(b * HH + h) * DKK + dk) * SS + s;
                    dst[0]  = __float2half_rn(v0);
                    dst[SS] = __float2half_rn(v1);
                } else {
                    int b = m >> 11, s = m & (SS - 1);
                    int h = n >> 6, dk = n & 63;  // even
                    float p = (float)pos[s];
                    float inv = expf(-(float)dk * LN_TH_OVER);
                    float sn, cs;
                    sincosf(p * inv, &sn, &cs);
                    float o0 = v0 * cs - v1 * sn;
                    float o1 = v0 * sn + v1 * cs;
                    if (z == 0) { o0 *= QSCALE; o1 *= QSCALE; }
                    __half* dst = (z == 0 ? g_Qh : g_Kh)
                               + (((size_t)(b * HH + h) * SS + s) * DKK + dk);
                    *(uint32_t*)dst = packh2(o0, o1);
                }
            }
        }
    }
}

// ---------------------------------------------------------------------------
// FlashAttention-2 style fp16 tensor-core attention with LDSM + exp2 softmax.
// Q is pre-scaled by log2e/8 so scores are in log2 units.
// ---------------------------------------------------------------------------
__global__ __launch_bounds__(256, 2)
void attn_kernel()
{
    __shared__ __align__(16) char sK[2][64 * 128];
    __shared__ __align__(16) char sV[2][64 * 128];

    const int qt = (int)gridDim.x - 1 - (int)blockIdx.x;  // heavy tiles first
    const int h  = blockIdx.y;
    const int b  = blockIdx.z;
    const int tid = threadIdx.x;
    const int w = tid >> 5, lane = tid & 31;
    const int g = lane >> 2, c = lane & 3;
    const int q0w = qt * 128 + w * 16;

    const __half* Qbh = g_Qh + (size_t)(b * HH + h) * SS * DKK;
    const __half* Kbh = g_Kh + (size_t)(b * HH + h) * SS * DKK;
    const __half* Vbh = g_Vt + (size_t)(b * HH + h) * DKK * SS;

    const int r7 = lane & 7, qg = lane >> 3;
    const uint32_t sK0 = smem_u32(&sK[0][0]);
    const uint32_t sV0 = smem_u32(&sV[0][0]);
    const uint32_t swz0 = (uint32_t)(((qg     ^ r7) << 4) + r7 * 128);
    const uint32_t swz1 = (uint32_t)((((qg+4) ^ r7) << 4) + r7 * 128);

    uint32_t qreg[4][4];
#pragma unroll
    for (int kk = 0; kk < 4; kk++) {
        qreg[kk][0] = *(const uint32_t*)(Qbh + (q0w + g) * DKK + 16 * kk + 2 * c);
        qreg[kk][1] = *(const uint32_t*)(Qbh + (q0w + g + 8) * DKK + 16 * kk + 2 * c);
        qreg[kk][2] = *(const uint32_t*)(Qbh + (q0w + g) * DKK + 16 * kk + 2 * c + 8);
        qreg[kk][3] = *(const uint32_t*)(Qbh + (q0w + g + 8) * DKK + 16 * kk + 2 * c + 8);
    }

    float Oc[8][4];
#pragma unroll
    for (int n = 0; n < 8; n++)
#pragma unroll
        for (int i = 0; i < 4; i++) Oc[n][i] = 0.f;
    float mrow[2] = {-1e30f, -1e30f};
    float lrow[2] = {0.f, 0.f};

    auto load_kv = [&](int bufi, int kt) {
        int kv0 = kt * 64;
#pragma unroll
        for (int i = 0; i < 2; i++) {
            int idx = tid + i * 256;
            int r = idx >> 3;
            int ch = idx & 7;
            int dst = r * 128 + ((ch ^ (r & 7)) << 4);
            cp16(sK[bufi] + dst, Kbh + (size_t)(kv0 + r) * DKK + ch * 8);
            cp16(sV[bufi] + dst, Vbh + (size_t)r * SS + kv0 + ch * 8);
        }
    };

    const int ktmax = qt * 2 + 1;
    load_kv(0, 0);
    asm volatile("cp.async.commit_group;");

    int buf = 0;
    for (int kt = 0; kt <= ktmax; kt++) {
        if (kt < ktmax) {
            load_kv(buf ^ 1, kt + 1);
            asm volatile("cp.async.commit_group;");
            asm volatile("cp.async.wait_group 1;");
        } else {
            asm volatile("cp.async.wait_group 0;");
        }
        __syncthreads();

        const int kv0 = kt * 64;
        const uint32_t kb0 = sK0 + buf * 8192 + swz0;
        const uint32_t kb1 = sK0 + buf * 8192 + swz1;

        float Sc[8][4];
#pragma unroll
        for (int n = 0; n < 8; n++)
#pragma unroll
            for (int i = 0; i < 4; i++) Sc[n][i] = 0.f;

#pragma unroll
        for (int n = 0; n < 8; n++) {
            uint32_t b00, b01, b10, b11, b20, b21, b30, b31;
            ldsm_x4(b00, b01, b10, b11, kb0 + n * 1024);
            ldsm_x4(b20, b21, b30, b31, kb1 + n * 1024);
            mma_f16(Sc[n], qreg[0], b00, b01);
            mma_f16(Sc[n], qreg[1], b10, b11);
            mma_f16(Sc[n], qreg[2], b20, b21);
            mma_f16(Sc[n], qreg[3], b30, b31);
        }

        if (kv0 + 63 > q0w) {
            int r0 = q0w + g, r1 = q0w + g + 8;
#pragma unroll
            for (int n = 0; n < 8; n++) {
                int col = kv0 + n * 8 + 2 * c;
                if (col > r0)     Sc[n][0] = -1e30f;
                if (col + 1 > r0) Sc[n][1] = -1e30f;
                if (col > r1)     Sc[n][2] = -1e30f;
                if (col + 1 > r1) Sc[n][3] = -1e30f;
            }
        }

        float mx0 = Sc[0][0], mx1 = Sc[0][2];
#pragma unroll
        for (int n = 0; n < 8; n++) {
            mx0 = fmaxf(mx0, fmaxf(Sc[n][0], Sc[n][1]));
            mx1 = fmaxf(mx1, fmaxf(Sc[n][2], Sc[n][3]));
        }
        mx0 = fmaxf(mx0, __shfl_xor_sync(0xffffffffu, mx0, 1));
        mx0 = fmaxf(mx0, __shfl_xor_sync(0xffffffffu, mx0, 2));
        mx1 = fmaxf(mx1, __shfl_xor_sync(0xffffffffu, mx1, 1));
        mx1 = fmaxf(mx1, __shfl_xor_sync(0xffffffffu, mx1, 2));

        float mn0 = fmaxf(mrow[0], mx0);
        float mn1 = fmaxf(mrow[1], mx1);
        float a0 = exp2f(mrow[0] - mn0);
        float a1 = exp2f(mrow[1] - mn1);

        float rs0 = 0.f, rs1 = 0.f;
#pragma unroll
        for (int n = 0; n < 8; n++) {
            Sc[n][0] = exp2f(Sc[n][0] - mn0);
            Sc[n][1] = exp2f(Sc[n][1] - mn0);
            Sc[n][2] = exp2f(Sc[n][2] - mn1);
            Sc[n][3] = exp2f(Sc[n][3] - mn1);
            rs0 += Sc[n][0] + Sc[n][1];
            rs1 += Sc[n][2] + Sc[n][3];
        }
        rs0 += __shfl_xor_sync(0xffffffffu, rs0, 1);
        rs0 += __shfl_xor_sync(0xffffffffu, rs0, 2);
        rs1 += __shfl_xor_sync(0xffffffffu, rs1, 1);
        rs1 += __shfl_xor_sync(0xffffffffu, rs1, 2);

        lrow[0] = lrow[0] * a0 + rs0;
        lrow[1] = lrow[1] * a1 + rs1;
        mrow[0] = mn0; mrow[1] = mn1;

#pragma unroll
        for (int n = 0; n < 8; n++) {
            Oc[n][0] *= a0; Oc[n][1] *= a0;
            Oc[n][2] *= a1; Oc[n][3] *= a1;
        }

        uint32_t pa[4][4];
#pragma unroll
        for (int kk = 0; kk < 4; kk++) {
            pa[kk][0] = packh2(Sc[2 * kk][0],     Sc[2 * kk][1]);
            pa[kk][1] = packh2(Sc[2 * kk][2],     Sc[2 * kk][3]);
            pa[kk][2] = packh2(Sc[2 * kk + 1][0], Sc[2 * kk + 1][1]);
            pa[kk][3] = packh2(Sc[2 * kk + 1][2], Sc[2 * kk + 1][3]);
        }

        const uint32_t vb0 = sV0 + buf * 8192 + swz0;
        const uint32_t vb1 = sV0 + buf * 8192 + swz1;
#pragma unroll
        for (int nd = 0; nd < 8; nd++) {
            uint32_t b00, b01, b10, b11, b20, b21, b30, b31;
            ldsm_x4(b00, b01, b10, b11, vb0 + nd * 1024);
            ldsm_x4(b20, b21, b30, b31, vb1 + nd * 1024);
            mma_f16(Oc[nd], pa[0], b00, b01);
            mma_f16(Oc[nd], pa[1], b10, b11);
            mma_f16(Oc[nd], pa[2], b20, b21);
            mma_f16(Oc[nd], pa[3], b30, b31);
        }

        __syncthreads();
        buf ^= 1;
    }

    float inv0 = 1.f / lrow[0];
    float inv1 = 1.f / lrow[1];
    __half* Cb0 = g_Ctxh + ((size_t)(b * SS + q0w + g) * DD + h * 64);
    __half* Cb1 = g_Ctxh + ((size_t)(b * SS + q0w + g + 8) * DD + h * 64);
#pragma unroll
    for (int nd = 0; nd < 8; nd++) {
        int col = nd * 8 + 2 * c;
        *(uint32_t*)(Cb0 + col) = packh2(Oc[nd][0] * inv0, Oc[nd][1] * inv0);
        *(uint32_t*)(Cb1 + col) = packh2(Oc[nd][2] * inv1, Oc[nd][3] * inv1);
    }
}

// ---------------------------------------------------------------------------
extern "C" void kernel_launch(void* const* d_in, const int* in_sizes, int n_in,
                              void* d_out, int out_size)
{
    const float* x  = (const float*)d_in[0];
    const float* Wq = (const float*)d_in[1];
    const float* Wk = (const float*)d_in[2];
    const float* Wv = (const float*)d_in[3];
    const float* Wo = (const float*)d_in[4];
    const int* pos  = (const int*)d_in[5];
    float* out = (float*)d_out;

    void* xh_ptr = nullptr, *ctxh_ptr = nullptr;
    cudaGetSymbolAddress(&xh_ptr, g_xh);
    cudaGetSymbolAddress(&ctxh_ptr, g_Ctxh);
    __half* xh = (__half*)xh_ptr;

    static int attr_set = 0;
    if (!attr_set) {
        cudaFuncSetAttribute(gemm3_kernel<0>,
                             cudaFuncAttributeMaxDynamicSharedMemorySize, GSMEM_TOTAL);
        cudaFuncSetAttribute(gemm3_kernel<1>,
                             cudaFuncAttributeMaxDynamicSharedMemorySize, GSMEM_TOTAL);
        attr_set = 1;
    }

    cvt_kernel<<<2048, 256>>>(x, xh, M_TOTAL * DD / 4);
    {
        dim3 cg(512, 1, 4);
        cvtw_kernel<<<cg, 256>>>(Wq, Wk, Wv, Wo, DD * DD / 4);
    }

    dim3 gq(DD / 128, M_TOTAL / 128, 3);   // 8 x 64 x 3
    gemm3_kernel<0><<<gq, 256, GSMEM_TOTAL>>>(xh, nullptr, pos);

    dim3 agrid(SS / 128, HH, BB);
    attn_kernel<<<agrid, 256>>>();

    dim3 go(DD / 128, M_TOTAL / 128);      // 8 x 64
    gemm3_kernel<1><<<go, 256, GSMEM_TOTAL>>>((const __half*)ctxh_ptr, out, pos);
}

// round 10
// speedup vs baseline: 1.9887x; 1.0384x over previous
#include <cuda_runtime.h>
#include <cuda_fp16.h>
#include <math.h>
#include <stdint.h>

#define BB 4
#define SS 2048
#define DD 1024
#define HH 16
#define DKK 64
#define M_TOTAL (BB*SS)

// Scratch (device globals; allocation-free per harness rules)
__device__ __half g_xh [M_TOTAL*DD];     // fp16 copy of x
__device__ __half g_Wh [4*DD*DD];        // fp16 copies of Wq,Wk,Wv,Wo
__device__ __half g_Qh [BB*HH*SS*DKK];   // [b,h,s,d], pre-scaled by log2e/8
__device__ __half g_Kh [BB*HH*SS*DKK];   // [b,h,s,d]
__device__ __half g_Vt [BB*HH*DKK*SS];   // [b,h,d,s]  (transposed V)
__device__ __half g_Ctxh[M_TOTAL*DD];    // fp16 context [b,s,D]

// ---------------------------------------------------------------------------
// helpers
// ---------------------------------------------------------------------------
__device__ __forceinline__ uint32_t smem_u32(const void* p) {
    uint32_t a;
    asm("{ .reg .u64 t; cvta.to.shared.u64 t, %1; cvt.u32.u64 %0, t; }"
        : "=r"(a) : "l"(p));
    return a;
}

__device__ __forceinline__ void mma_f16(float* c, const uint32_t* a,
                                        uint32_t b0, uint32_t b1) {
    asm volatile(
        "mma.sync.aligned.m16n8k16.row.col.f32.f16.f16.f32 "
        "{%0,%1,%2,%3},{%4,%5,%6,%7},{%8,%9},{%0,%1,%2,%3};"
        : "+f"(c[0]), "+f"(c[1]), "+f"(c[2]), "+f"(c[3])
        : "r"(a[0]), "r"(a[1]), "r"(a[2]), "r"(a[3]), "r"(b0), "r"(b1));
}

__device__ __forceinline__ void ldsm_x4(uint32_t& r0, uint32_t& r1,
                                        uint32_t& r2, uint32_t& r3, uint32_t addr) {
    asm volatile("ldmatrix.sync.aligned.m8n8.x4.shared.b16 {%0,%1,%2,%3}, [%4];"
                 : "=r"(r0), "=r"(r1), "=r"(r2), "=r"(r3) : "r"(addr));
}

__device__ __forceinline__ void cp16(void* smem, const void* g) {
    uint32_t s = smem_u32(smem);
    asm volatile("cp.async.cg.shared.global [%0], [%1], 16;" :: "r"(s), "l"(g));
}

__device__ __forceinline__ uint32_t packh2(float lo, float hi) {
    __half2 h = __floats2half2_rn(lo, hi);
    return *(uint32_t*)&h;
}

__device__ __forceinline__ uint32_t h2exp2(uint32_t x) {
    uint32_t r;
    asm("ex2.approx.f16x2 %0, %1;" : "=r"(r) : "r"(x));
    return r;
}

// ---------------------------------------------------------------------------
// fp32 -> fp16 conversions, 4 independent loads per thread (MLP=4).
// Requires n4 == 4 * gridDim.x * blockDim.x.
// ---------------------------------------------------------------------------
__global__ void cvt4_kernel(const float* __restrict__ src, __half* __restrict__ dst)
{
    const int t = blockIdx.x * blockDim.x + threadIdx.x;
    const int T = gridDim.x * blockDim.x;
    float4 v[4];
#pragma unroll
    for (int j = 0; j < 4; j++) v[j] = ((const float4*)src)[t + j * T];
#pragma unroll
    for (int j = 0; j < 4; j++)
        ((uint2*)dst)[t + j * T] = make_uint2(packh2(v[j].x, v[j].y),
                                             packh2(v[j].z, v[j].w));
}

__global__ void cvtw4_kernel(const float* W0, const float* W1,
                             const float* W2, const float* W3)
{
    const float* src = blockIdx.z == 0 ? W0 : blockIdx.z == 1 ? W1
                     : blockIdx.z == 2 ? W2 : W3;
    __half* dst = g_Wh + (size_t)blockIdx.z * DD * DD;
    const int t = blockIdx.x * blockDim.x + threadIdx.x;
    const int T = gridDim.x * blockDim.x;
    float4 v[4];
#pragma unroll
    for (int j = 0; j < 4; j++) v[j] = ((const float4*)src)[t + j * T];
#pragma unroll
    for (int j = 0; j < 4; j++)
        ((uint2*)dst)[t + j * T] = make_uint2(packh2(v[j].x, v[j].y),
                                             packh2(v[j].z, v[j].w));
}

// ---------------------------------------------------------------------------
// fp16 tensor-core GEMM (HMMA + LDSM), 3-stage cp.async pipeline, K-chunk 64.
// (unchanged from R9)
// ---------------------------------------------------------------------------
#define PITCHB 144
#define A_BYTES (128 * PITCHB)
#define STAGE_BYTES (2 * A_BYTES)
#define GSMEM_TOTAL (3 * STAGE_BYTES)

template<int MODE>
__global__ __launch_bounds__(256)
void gemm3_kernel(const __half* __restrict__ A, float* __restrict__ Cout,
                  const int* __restrict__ pos)
{
    extern __shared__ char dsm[];
    const int z = (MODE == 0) ? blockIdx.z : 3;
    const __half* __restrict__ W = g_Wh + (size_t)z * DD * DD;

    const int tid = threadIdx.x;
    const int m0 = blockIdx.y * 128;
    const int n0 = blockIdx.x * 128;
    const int w = tid >> 5, lane = tid & 31;
    const int wm = (w & 1) * 64;
    const int wn = (w >> 1) * 32;
    const int r = lane >> 2, c = lane & 3;
    const int l7 = lane & 7;

    const uint32_t sbase = smem_u32(dsm);
    const uint32_t a_off = (uint32_t)((wm + (lane & 15)) * PITCHB
                                      + ((lane & 16) ? 16 : 0));
    const uint32_t b_off = (uint32_t)(A_BYTES
                                      + (wn + l7 + ((lane & 16) ? 8 : 0)) * PITCHB
                                      + ((lane & 8) ? 16 : 0));

    float acc[4][4][4];
#pragma unroll
    for (int mt = 0; mt < 4; mt++)
#pragma unroll
        for (int nt = 0; nt < 4; nt++)
#pragma unroll
            for (int i = 0; i < 4; i++) acc[mt][nt][i] = 0.f;

    auto load_stage = [&](int st, int kt) {
        int k0 = kt * 64;
        char* sA = dsm + st * STAGE_BYTES;
        char* sB = sA + A_BYTES;
#pragma unroll
        for (int i = 0; i < 4; i++) {
            int idx = tid + i * 256;
            int row = idx >> 3;
            int ch = idx & 7;
            cp16(sA + row * PITCHB + ch * 16, A + (size_t)(m0 + row) * DD + k0 + ch * 8);
            cp16(sB + row * PITCHB + ch * 16, W + (size_t)(n0 + row) * DD + k0 + ch * 8);
        }
        asm volatile("cp.async.commit_group;");
    };

    const int KT = DD / 64;  // 16
    load_stage(0, 0);
    load_stage(1, 1);

    int st = 0;
    for (int kt = 0; kt < KT; kt++) {
        if (kt + 1 < KT) asm volatile("cp.async.wait_group 1;");
        else             asm volatile("cp.async.wait_group 0;");
        __syncthreads();

        if (kt + 2 < KT) {
            int nst = st + 2; if (nst >= 3) nst -= 3;
            load_stage(nst, kt + 2);
        }

        const uint32_t aBase = sbase + st * STAGE_BYTES + a_off;
        const uint32_t bBase = sbase + st * STAGE_BYTES + b_off;
#pragma unroll
        for (int kk = 0; kk < 4; kk++) {
            uint32_t af[4][4];
#pragma unroll
            for (int mt = 0; mt < 4; mt++)
                ldsm_x4(af[mt][0], af[mt][1], af[mt][2], af[mt][3],
                        aBase + mt * (16 * PITCHB) + kk * 32);
            uint32_t bf[4][2];
#pragma unroll
            for (int ntp = 0; ntp < 2; ntp++)
                ldsm_x4(bf[2*ntp][0], bf[2*ntp][1], bf[2*ntp+1][0], bf[2*ntp+1][1],
                        bBase + ntp * (16 * PITCHB) + kk * 32);
#pragma unroll
            for (int mt = 0; mt < 4; mt++)
#pragma unroll
                for (int nt = 0; nt < 4; nt++)
                    mma_f16(acc[mt][nt], af[mt], bf[nt][0], bf[nt][1]);
        }
        st++; if (st >= 3) st -= 3;
    }

    // ---------------- epilogue ----------------
    const float LN_TH_OVER = 9.210340372f / 64.0f;  // ln(10000)/64
    const float QSCALE = 0.125f * 1.44269504089f;   // fold log2e for exp2 softmax
#pragma unroll
    for (int mt = 0; mt < 4; mt++) {
#pragma unroll
        for (int nt = 0; nt < 4; nt++) {
            int n = n0 + wn + nt * 8 + c * 2;       // even column
#pragma unroll
            for (int half = 0; half < 2; half++) {
                int m = m0 + wm + mt * 16 + r + half * 8;
                float v0 = acc[mt][nt][half * 2];
                float v1 = acc[mt][nt][half * 2 + 1];
                if (MODE == 1) {
                    *(float2*)(Cout + (size_t)m * DD + n) = make_float2(v0, v1);
                } else if (z == 2) {
                    int b = m >> 11, s = m & (SS - 1);
                    int h = n >> 6, dk = n & 63;
                    __half* dst = g_Vt + ((size_t)(b * HH + h) * DKK + dk) * SS + s;
                    dst[0]  = __float2half_rn(v0);
                    dst[SS] = __float2half_rn(v1);
                } else {
                    int b = m >> 11, s = m & (SS - 1);
                    int h = n >> 6, dk = n & 63;  // even
                    float p = (float)pos[s];
                    float inv = expf(-(float)dk * LN_TH_OVER);
                    float sn, cs;
                    sincosf(p * inv, &sn, &cs);
                    float o0 = v0 * cs - v1 * sn;
                    float o1 = v0 * sn + v1 * cs;
                    if (z == 0) { o0 *= QSCALE; o1 *= QSCALE; }
                    __half* dst = (z == 0 ? g_Qh : g_Kh)
                               + (((size_t)(b * HH + h) * SS + s) * DKK + dk);
                    *(uint32_t*)dst = packh2(o0, o1);
                }
            }
        }
    }
}

// ---------------------------------------------------------------------------
// FlashAttention-2 attention: LDSM + fp16x2 exp2 + tensor-core row sums.
// Q pre-scaled by log2e/8 (scores in log2 units).
// ---------------------------------------------------------------------------
#define H2_ONES 0x3C003C00u

__global__ __launch_bounds__(256, 2)
void attn_kernel()
{
    __shared__ __align__(16) char sK[2][64 * 128];
    __shared__ __align__(16) char sV[2][64 * 128];

    const int qt = (int)gridDim.x - 1 - (int)blockIdx.x;  // heavy tiles first
    const int h  = blockIdx.y;
    const int b  = blockIdx.z;
    const int tid = threadIdx.x;
    const int w = tid >> 5, lane = tid & 31;
    const int g = lane >> 2, c = lane & 3;
    const int q0w = qt * 128 + w * 16;

    const __half* Qbh = g_Qh + (size_t)(b * HH + h) * SS * DKK;
    const __half* Kbh = g_Kh + (size_t)(b * HH + h) * SS * DKK;
    const __half* Vbh = g_Vt + (size_t)(b * HH + h) * DKK * SS;

    const int r7 = lane & 7, qg = lane >> 3;
    const uint32_t sK0 = smem_u32(&sK[0][0]);
    const uint32_t sV0 = smem_u32(&sV[0][0]);
    const uint32_t swz0 = (uint32_t)(((qg     ^ r7) << 4) + r7 * 128);
    const uint32_t swz1 = (uint32_t)((((qg+4) ^ r7) << 4) + r7 * 128);

    uint32_t qreg[4][4];
#pragma unroll
    for (int kk = 0; kk < 4; kk++) {
        qreg[kk][0] = *(const uint32_t*)(Qbh + (q0w + g) * DKK + 16 * kk + 2 * c);
        qreg[kk][1] = *(const uint32_t*)(Qbh + (q0w + g + 8) * DKK + 16 * kk + 2 * c);
        qreg[kk][2] = *(const uint32_t*)(Qbh + (q0w + g) * DKK + 16 * kk + 2 * c + 8);
        qreg[kk][3] = *(const uint32_t*)(Qbh + (q0w + g + 8) * DKK + 16 * kk + 2 * c + 8);
    }

    float Oc[8][4];
#pragma unroll
    for (int n = 0; n < 8; n++)
#pragma unroll
        for (int i = 0; i < 4; i++) Oc[n][i] = 0.f;
    float mrow[2] = {-1e30f, -1e30f};
    float lrow[2] = {0.f, 0.f};

    auto load_kv = [&](int bufi, int kt) {
        int kv0 = kt * 64;
#pragma unroll
        for (int i = 0; i < 2; i++) {
            int idx = tid + i * 256;
            int r = idx >> 3;
            int ch = idx & 7;
            int dst = r * 128 + ((ch ^ (r & 7)) << 4);
            cp16(sK[bufi] + dst, Kbh + (size_t)(kv0 + r) * DKK + ch * 8);
            cp16(sV[bufi] + dst, Vbh + (size_t)r * SS + kv0 + ch * 8);
        }
    };

    const int ktmax = qt * 2 + 1;
    load_kv(0, 0);
    asm volatile("cp.async.commit_group;");

    int buf = 0;
    for (int kt = 0; kt <= ktmax; kt++) {
        if (kt < ktmax) {
            load_kv(buf ^ 1, kt + 1);
            asm volatile("cp.async.commit_group;");
            asm volatile("cp.async.wait_group 1;");
        } else {
            asm volatile("cp.async.wait_group 0;");
        }
        __syncthreads();

        const int kv0 = kt * 64;
        const uint32_t kb0 = sK0 + buf * 8192 + swz0;
        const uint32_t kb1 = sK0 + buf * 8192 + swz1;

        float Sc[8][4];
#pragma unroll
        for (int n = 0; n < 8; n++)
#pragma unroll
            for (int i = 0; i < 4; i++) Sc[n][i] = 0.f;

#pragma unroll
        for (int n = 0; n < 8; n++) {
            uint32_t b00, b01, b10, b11, b20, b21, b30, b31;
            ldsm_x4(b00, b01, b10, b11, kb0 + n * 1024);
            ldsm_x4(b20, b21, b30, b31, kb1 + n * 1024);
            mma_f16(Sc[n], qreg[0], b00, b01);
            mma_f16(Sc[n], qreg[1], b10, b11);
            mma_f16(Sc[n], qreg[2], b20, b21);
            mma_f16(Sc[n], qreg[3], b30, b31);
        }

        if (kv0 + 63 > q0w) {
            int r0 = q0w + g, r1 = q0w + g + 8;
#pragma unroll
            for (int n = 0; n < 8; n++) {
                int col = kv0 + n * 8 + 2 * c;
                if (col > r0)     Sc[n][0] = -1e30f;
                if (col + 1 > r0) Sc[n][1] = -1e30f;
                if (col > r1)     Sc[n][2] = -1e30f;
                if (col + 1 > r1) Sc[n][3] = -1e30f;
            }
        }

        // ---- row max (quad reduce) ----
        float mx0 = Sc[0][0], mx1 = Sc[0][2];
#pragma unroll
        for (int n = 0; n < 8; n++) {
            mx0 = fmaxf(mx0, fmaxf(Sc[n][0], Sc[n][1]));
            mx1 = fmaxf(mx1, fmaxf(Sc[n][2], Sc[n][3]));
        }
        mx0 = fmaxf(mx0, __shfl_xor_sync(0xffffffffu, mx0, 1));
        mx0 = fmaxf(mx0, __shfl_xor_sync(0xffffffffu, mx0, 2));
        mx1 = fmaxf(mx1, __shfl_xor_sync(0xffffffffu, mx1, 1));
        mx1 = fmaxf(mx1, __shfl_xor_sync(0xffffffffu, mx1, 2));

        float mn0 = fmaxf(mrow[0], mx0);
        float mn1 = fmaxf(mrow[1], mx1);
        float a0 = exp2f(mrow[0] - mn0);
        float a1 = exp2f(mrow[1] - mn1);
        mrow[0] = mn0; mrow[1] = mn1;

        // ---- P = exp2(S - m) directly into fp16 A-fragments ----
        uint32_t pa[4][4];
#pragma unroll
        for (int n = 0; n < 8; n++) {
            uint32_t e0 = h2exp2(packh2(Sc[n][0] - mn0, Sc[n][1] - mn0));
            uint32_t e1 = h2exp2(packh2(Sc[n][2] - mn1, Sc[n][3] - mn1));
            pa[n >> 1][(n & 1) ? 2 : 0] = e0;
            pa[n >> 1][(n & 1) ? 3 : 1] = e1;
        }

        // ---- row sums via mma with ones (fp32 exact sum of fp16 P) ----
        float rsum[4] = {0.f, 0.f, 0.f, 0.f};
#pragma unroll
        for (int kk = 0; kk < 4; kk++)
            mma_f16(rsum, pa[kk], H2_ONES, H2_ONES);

        lrow[0] = lrow[0] * a0 + rsum[0];
        lrow[1] = lrow[1] * a1 + rsum[2];

#pragma unroll
        for (int n = 0; n < 8; n++) {
            Oc[n][0] *= a0; Oc[n][1] *= a0;
            Oc[n][2] *= a1; Oc[n][3] *= a1;
        }

        // ---- O += P V ----
        const uint32_t vb0 = sV0 + buf * 8192 + swz0;
        const uint32_t vb1 = sV0 + buf * 8192 + swz1;
#pragma unroll
        for (int nd = 0; nd < 8; nd++) {
            uint32_t b00, b01, b10, b11, b20, b21, b30, b31;
            ldsm_x4(b00, b01, b10, b11, vb0 + nd * 1024);
            ldsm_x4(b20, b21, b30, b31, vb1 + nd * 1024);
            mma_f16(Oc[nd], pa[0], b00, b01);
            mma_f16(Oc[nd], pa[1], b10, b11);
            mma_f16(Oc[nd], pa[2], b20, b21);
            mma_f16(Oc[nd], pa[3], b30, b31);
        }

        __syncthreads();
        buf ^= 1;
    }

    float inv0 = 1.f / lrow[0];
    float inv1 = 1.f / lrow[1];
    __half* Cb0 = g_Ctxh + ((size_t)(b * SS + q0w + g) * DD + h * 64);
    __half* Cb1 = g_Ctxh + ((size_t)(b * SS + q0w + g + 8) * DD + h * 64);
#pragma unroll
    for (int nd = 0; nd < 8; nd++) {
        int col = nd * 8 + 2 * c;
        *(uint32_t*)(Cb0 + col) = packh2(Oc[nd][0] * inv0, Oc[nd][1] * inv0);
        *(uint32_t*)(Cb1 + col) = packh2(Oc[nd][2] * inv1, Oc[nd][3] * inv1);
    }
}

// ---------------------------------------------------------------------------
extern "C" void kernel_launch(void* const* d_in, const int* in_sizes, int n_in,
                              void* d_out, int out_size)
{
    const float* x  = (const float*)d_in[0];
    const float* Wq = (const float*)d_in[1];
    const float* Wk = (const float*)d_in[2];
    const float* Wv = (const float*)d_in[3];
    const float* Wo = (const float*)d_in[4];
    const int* pos  = (const int*)d_in[5];
    float* out = (float*)d_out;

    void* xh_ptr = nullptr, *ctxh_ptr = nullptr;
    cudaGetSymbolAddress(&xh_ptr, g_xh);
    cudaGetSymbolAddress(&ctxh_ptr, g_Ctxh);
    __half* xh = (__half*)xh_ptr;

    static int attr_set = 0;
    if (!attr_set) {
        cudaFuncSetAttribute(gemm3_kernel<0>,
                             cudaFuncAttributeMaxDynamicSharedMemorySize, GSMEM_TOTAL);
        cudaFuncSetAttribute(gemm3_kernel<1>,
                             cudaFuncAttributeMaxDynamicSharedMemorySize, GSMEM_TOTAL);
        attr_set = 1;
    }

    // conversions (each thread: 4 independent float4 loads)
    cvt4_kernel<<<2048, 256>>>(x, xh);              // 2048*256*4 = 2,097,152 = n4
    {
        dim3 cg(256, 1, 4);                          // 256*256*4 = 262,144 = n4
        cvtw4_kernel<<<cg, 256>>>(Wq, Wk, Wv, Wo);
    }

    dim3 gq(DD / 128, M_TOTAL / 128, 3);   // 8 x 64 x 3
    gemm3_kernel<0><<<gq, 256, GSMEM_TOTAL>>>(xh, nullptr, pos);

    dim3 agrid(SS / 128, HH, BB);
    attn_kernel<<<agrid, 256>>>();

    dim3 go(DD / 128, M_TOTAL / 128);      // 8 x 64
    gemm3_kernel<1><<<go, 256, GSMEM_TOTAL>>>((const __half*)ctxh_ptr, out, pos);
}

// round 11
// speedup vs baseline: 2.0404x; 1.0260x over previous
#include <cuda_runtime.h>
#include <cuda_fp16.h>
#include <math.h>
#include <stdint.h>

#define BB 4
#define SS 2048
#define DD 1024
#define HH 16
#define DKK 64
#define M_TOTAL (BB*SS)

// Scratch (device globals; allocation-free per harness rules)
__device__ __half g_xh [M_TOTAL*DD];     // fp16 copy of x
__device__ __half g_Wh [4*DD*DD];        // fp16 copies of Wq,Wk,Wv,Wo
__device__ __half g_Qh [BB*HH*SS*DKK];   // [b,h,s,d], pre-scaled by log2e/8
__device__ __half g_Kh [BB*HH*SS*DKK];   // [b,h,s,d]
__device__ __half g_Vt [BB*HH*DKK*SS];   // [b,h,d,s]  (transposed V)
__device__ __half g_Ctxh[M_TOTAL*DD];    // fp16 context [b,s,D]

// ---------------------------------------------------------------------------
// helpers
// ---------------------------------------------------------------------------
__device__ __forceinline__ uint32_t smem_u32(const void* p) {
    uint32_t a;
    asm("{ .reg .u64 t; cvta.to.shared.u64 t, %1; cvt.u32.u64 %0, t; }"
        : "=r"(a) : "l"(p));
    return a;
}

__device__ __forceinline__ void mma_f16(float* c, const uint32_t* a,
                                        uint32_t b0, uint32_t b1) {
    asm volatile(
        "mma.sync.aligned.m16n8k16.row.col.f32.f16.f16.f32 "
        "{%0,%1,%2,%3},{%4,%5,%6,%7},{%8,%9},{%0,%1,%2,%3};"
        : "+f"(c[0]), "+f"(c[1]), "+f"(c[2]), "+f"(c[3])
        : "r"(a[0]), "r"(a[1]), "r"(a[2]), "r"(a[3]), "r"(b0), "r"(b1));
}

__device__ __forceinline__ void ldsm_x4(uint32_t& r0, uint32_t& r1,
                                        uint32_t& r2, uint32_t& r3, uint32_t addr) {
    asm volatile("ldmatrix.sync.aligned.m8n8.x4.shared.b16 {%0,%1,%2,%3}, [%4];"
                 : "=r"(r0), "=r"(r1), "=r"(r2), "=r"(r3) : "r"(addr));
}

__device__ __forceinline__ void cp16(void* smem, const void* g) {
    uint32_t s = smem_u32(smem);
    asm volatile("cp.async.cg.shared.global [%0], [%1], 16;" :: "r"(s), "l"(g));
}

__device__ __forceinline__ uint32_t packh2(float lo, float hi) {
    __half2 h = __floats2half2_rn(lo, hi);
    return *(uint32_t*)&h;
}

__device__ __forceinline__ uint32_t h2exp2(uint32_t x) {
    uint32_t r;
    asm("ex2.approx.f16x2 %0, %1;" : "=r"(r) : "r"(x));
    return r;
}

// ---------------------------------------------------------------------------
// fp32 -> fp16 conversions (MLP=4)
// ---------------------------------------------------------------------------
__global__ void cvt4_kernel(const float* __restrict__ src, __half* __restrict__ dst)
{
    const int t = blockIdx.x * blockDim.x + threadIdx.x;
    const int T = gridDim.x * blockDim.x;
    float4 v[4];
#pragma unroll
    for (int j = 0; j < 4; j++) v[j] = ((const float4*)src)[t + j * T];
#pragma unroll
    for (int j = 0; j < 4; j++)
        ((uint2*)dst)[t + j * T] = make_uint2(packh2(v[j].x, v[j].y),
                                             packh2(v[j].z, v[j].w));
}

__global__ void cvtw4_kernel(const float* W0, const float* W1,
                             const float* W2, const float* W3)
{
    const float* src = blockIdx.z == 0 ? W0 : blockIdx.z == 1 ? W1
                     : blockIdx.z == 2 ? W2 : W3;
    __half* dst = g_Wh + (size_t)blockIdx.z * DD * DD;
    const int t = blockIdx.x * blockDim.x + threadIdx.x;
    const int T = gridDim.x * blockDim.x;
    float4 v[4];
#pragma unroll
    for (int j = 0; j < 4; j++) v[j] = ((const float4*)src)[t + j * T];
#pragma unroll
    for (int j = 0; j < 4; j++)
        ((uint2*)dst)[t + j * T] = make_uint2(packh2(v[j].x, v[j].y),
                                             packh2(v[j].z, v[j].w));
}

// ---------------------------------------------------------------------------
// fp16 tensor-core GEMM (HMMA + LDSM), 3-stage cp.async, K-chunk 64 (R9).
// ---------------------------------------------------------------------------
#define PITCHB 144
#define A_BYTES (128 * PITCHB)
#define STAGE_BYTES (2 * A_BYTES)
#define GSMEM_TOTAL (3 * STAGE_BYTES)

template<int MODE>
__global__ __launch_bounds__(256)
void gemm3_kernel(const __half* __restrict__ A, float* __restrict__ Cout,
                  const int* __restrict__ pos)
{
    extern __shared__ char dsm[];
    const int z = (MODE == 0) ? blockIdx.z : 3;
    const __half* __restrict__ W = g_Wh + (size_t)z * DD * DD;

    const int tid = threadIdx.x;
    const int m0 = blockIdx.y * 128;
    const int n0 = blockIdx.x * 128;
    const int w = tid >> 5, lane = tid & 31;
    const int wm = (w & 1) * 64;
    const int wn = (w >> 1) * 32;
    const int r = lane >> 2, c = lane & 3;
    const int l7 = lane & 7;

    const uint32_t sbase = smem_u32(dsm);
    const uint32_t a_off = (uint32_t)((wm + (lane & 15)) * PITCHB
                                      + ((lane & 16) ? 16 : 0));
    const uint32_t b_off = (uint32_t)(A_BYTES
                                      + (wn + l7 + ((lane & 16) ? 8 : 0)) * PITCHB
                                      + ((lane & 8) ? 16 : 0));

    float acc[4][4][4];
#pragma unroll
    for (int mt = 0; mt < 4; mt++)
#pragma unroll
        for (int nt = 0; nt < 4; nt++)
#pragma unroll
            for (int i = 0; i < 4; i++) acc[mt][nt][i] = 0.f;

    auto load_stage = [&](int st, int kt) {
        int k0 = kt * 64;
        char* sA = dsm + st * STAGE_BYTES;
        char* sB = sA + A_BYTES;
#pragma unroll
        for (int i = 0; i < 4; i++) {
            int idx = tid + i * 256;
            int row = idx >> 3;
            int ch = idx & 7;
            cp16(sA + row * PITCHB + ch * 16, A + (size_t)(m0 + row) * DD + k0 + ch * 8);
            cp16(sB + row * PITCHB + ch * 16, W + (size_t)(n0 + row) * DD + k0 + ch * 8);
        }
        asm volatile("cp.async.commit_group;");
    };

    const int KT = DD / 64;  // 16
    load_stage(0, 0);
    load_stage(1, 1);

    int st = 0;
    for (int kt = 0; kt < KT; kt++) {
        if (kt + 1 < KT) asm volatile("cp.async.wait_group 1;");
        else             asm volatile("cp.async.wait_group 0;");
        __syncthreads();

        if (kt + 2 < KT) {
            int nst = st + 2; if (nst >= 3) nst -= 3;
            load_stage(nst, kt + 2);
        }

        const uint32_t aBase = sbase + st * STAGE_BYTES + a_off;
        const uint32_t bBase = sbase + st * STAGE_BYTES + b_off;
#pragma unroll
        for (int kk = 0; kk < 4; kk++) {
            uint32_t af[4][4];
#pragma unroll
            for (int mt = 0; mt < 4; mt++)
                ldsm_x4(af[mt][0], af[mt][1], af[mt][2], af[mt][3],
                        aBase + mt * (16 * PITCHB) + kk * 32);
            uint32_t bf[4][2];
#pragma unroll
            for (int ntp = 0; ntp < 2; ntp++)
                ldsm_x4(bf[2*ntp][0], bf[2*ntp][1], bf[2*ntp+1][0], bf[2*ntp+1][1],
                        bBase + ntp * (16 * PITCHB) + kk * 32);
#pragma unroll
            for (int mt = 0; mt < 4; mt++)
#pragma unroll
                for (int nt = 0; nt < 4; nt++)
                    mma_f16(acc[mt][nt], af[mt], bf[nt][0], bf[nt][1]);
        }
        st++; if (st >= 3) st -= 3;
    }

    // ---------------- epilogue ----------------
    const float LN_TH_OVER = 9.210340372f / 64.0f;  // ln(10000)/64
    const float QSCALE = 0.125f * 1.44269504089f;   // fold log2e for exp2 softmax
#pragma unroll
    for (int mt = 0; mt < 4; mt++) {
#pragma unroll
        for (int nt = 0; nt < 4; nt++) {
            int n = n0 + wn + nt * 8 + c * 2;       // even column
#pragma unroll
            for (int half = 0; half < 2; half++) {
                int m = m0 + wm + mt * 16 + r + half * 8;
                float v0 = acc[mt][nt][half * 2];
                float v1 = acc[mt][nt][half * 2 + 1];
                if (MODE == 1) {
                    *(float2*)(Cout + (size_t)m * DD + n) = make_float2(v0, v1);
                } else if (z == 2) {
                    int b = m >> 11, s = m & (SS - 1);
                    int h = n >> 6, dk = n & 63;
                    __half* dst = g_Vt + ((size_t)(b * HH + h) * DKK + dk) * SS + s;
                    dst[0]  = __float2half_rn(v0);
                    dst[SS] = __float2half_rn(v1);
                } else {
                    int b = m >> 11, s = m & (SS - 1);
                    int h = n >> 6, dk = n & 63;  // even
                    float p = (float)pos[s];
                    float inv = expf(-(float)dk * LN_TH_OVER);
                    float sn, cs;
                    sincosf(p * inv, &sn, &cs);
                    float o0 = v0 * cs - v1 * sn;
                    float o1 = v0 * sn + v1 * cs;
                    if (z == 0) { o0 *= QSCALE; o1 *= QSCALE; }
                    __half* dst = (z == 0 ? g_Qh : g_Kh)
                               + (((size_t)(b * HH + h) * SS + s) * DKK + dk);
                    *(uint32_t*)dst = packh2(o0, o1);
                }
            }
        }
    }
}

// ---------------------------------------------------------------------------
// FlashAttention-2 attention: 6-slot KV ring, one barrier per 2 tiles,
// LDSM + fp16x2 exp2 + tensor-core row sums. Q pre-scaled by log2e/8.
// Dynamic smem: K 6x8KB + V 6x8KB = 96KB.
// ---------------------------------------------------------------------------
#define H2_ONES 0x3C003C00u
#define TSLOT 8192
#define ASMEM_TOTAL (12 * TSLOT)

__global__ __launch_bounds__(256, 2)
void attn_kernel()
{
    extern __shared__ char adsm[];
    char* sK = adsm;                 // 6 x 8192
    char* sV = adsm + 6 * TSLOT;     // 6 x 8192

    const int qt = (int)gridDim.x - 1 - (int)blockIdx.x;  // heavy tiles first
    const int h  = blockIdx.y;
    const int b  = blockIdx.z;
    const int tid = threadIdx.x;
    const int w = tid >> 5, lane = tid & 31;
    const int g = lane >> 2, c = lane & 3;
    const int q0w = qt * 128 + w * 16;

    const __half* Qbh = g_Qh + (size_t)(b * HH + h) * SS * DKK;
    const __half* Kbh = g_Kh + (size_t)(b * HH + h) * SS * DKK;
    const __half* Vbh = g_Vt + (size_t)(b * HH + h) * DKK * SS;

    const int r7 = lane & 7, qg = lane >> 3;
    const uint32_t sK0 = smem_u32(sK);
    const uint32_t sV0 = smem_u32(sV);
    const uint32_t swz0 = (uint32_t)(((qg     ^ r7) << 4) + r7 * 128);
    const uint32_t swz1 = (uint32_t)((((qg+4) ^ r7) << 4) + r7 * 128);

    uint32_t qreg[4][4];
#pragma unroll
    for (int kk = 0; kk < 4; kk++) {
        qreg[kk][0] = *(const uint32_t*)(Qbh + (q0w + g) * DKK + 16 * kk + 2 * c);
        qreg[kk][1] = *(const uint32_t*)(Qbh + (q0w + g + 8) * DKK + 16 * kk + 2 * c);
        qreg[kk][2] = *(const uint32_t*)(Qbh + (q0w + g) * DKK + 16 * kk + 2 * c + 8);
        qreg[kk][3] = *(const uint32_t*)(Qbh + (q0w + g + 8) * DKK + 16 * kk + 2 * c + 8);
    }

    float Oc[8][4];
#pragma unroll
    for (int n = 0; n < 8; n++)
#pragma unroll
        for (int i = 0; i < 4; i++) Oc[n][i] = 0.f;
    float mrow[2] = {-1e30f, -1e30f};
    float lrow[2] = {0.f, 0.f};

    // one tile (K+V) -> one commit group
    auto load_kv = [&](int slot, int kt) {
        int kv0 = kt * 64;
#pragma unroll
        for (int i = 0; i < 2; i++) {
            int idx = tid + i * 256;
            int r = idx >> 3;
            int ch = idx & 7;
            int dst = slot * TSLOT + r * 128 + ((ch ^ (r & 7)) << 4);
            cp16(sK + dst, Kbh + (size_t)(kv0 + r) * DKK + ch * 8);
            cp16(sV + dst, Vbh + (size_t)r * SS + kv0 + ch * 8);
        }
        asm volatile("cp.async.commit_group;");
    };

    // compute one KV tile from ring slot
    auto body = [&](int slot, int kt) {
        const int kv0 = kt * 64;
        const uint32_t kb0 = sK0 + slot * TSLOT + swz0;
        const uint32_t kb1 = sK0 + slot * TSLOT + swz1;

        float Sc[8][4];
#pragma unroll
        for (int n = 0; n < 8; n++)
#pragma unroll
            for (int i = 0; i < 4; i++) Sc[n][i] = 0.f;

#pragma unroll
        for (int n = 0; n < 8; n++) {
            uint32_t b00, b01, b10, b11, b20, b21, b30, b31;
            ldsm_x4(b00, b01, b10, b11, kb0 + n * 1024);
            ldsm_x4(b20, b21, b30, b31, kb1 + n * 1024);
            mma_f16(Sc[n], qreg[0], b00, b01);
            mma_f16(Sc[n], qreg[1], b10, b11);
            mma_f16(Sc[n], qreg[2], b20, b21);
            mma_f16(Sc[n], qreg[3], b30, b31);
        }

        if (kv0 + 63 > q0w) {
            int r0 = q0w + g, r1 = q0w + g + 8;
#pragma unroll
            for (int n = 0; n < 8; n++) {
                int col = kv0 + n * 8 + 2 * c;
                if (col > r0)     Sc[n][0] = -1e30f;
                if (col + 1 > r0) Sc[n][1] = -1e30f;
                if (col > r1)     Sc[n][2] = -1e30f;
                if (col + 1 > r1) Sc[n][3] = -1e30f;
            }
        }

        float mx0 = Sc[0][0], mx1 = Sc[0][2];
#pragma unroll
        for (int n = 0; n < 8; n++) {
            mx0 = fmaxf(mx0, fmaxf(Sc[n][0], Sc[n][1]));
            mx1 = fmaxf(mx1, fmaxf(Sc[n][2], Sc[n][3]));
        }
        mx0 = fmaxf(mx0, __shfl_xor_sync(0xffffffffu, mx0, 1));
        mx0 = fmaxf(mx0, __shfl_xor_sync(0xffffffffu, mx0, 2));
        mx1 = fmaxf(mx1, __shfl_xor_sync(0xffffffffu, mx1, 1));
        mx1 = fmaxf(mx1, __shfl_xor_sync(0xffffffffu, mx1, 2));

        float mn0 = fmaxf(mrow[0], mx0);
        float mn1 = fmaxf(mrow[1], mx1);
        float a0 = exp2f(mrow[0] - mn0);
        float a1 = exp2f(mrow[1] - mn1);
        mrow[0] = mn0; mrow[1] = mn1;

        uint32_t pa[4][4];
#pragma unroll
        for (int n = 0; n < 8; n++) {
            uint32_t e0 = h2exp2(packh2(Sc[n][0] - mn0, Sc[n][1] - mn0));
            uint32_t e1 = h2exp2(packh2(Sc[n][2] - mn1, Sc[n][3] - mn1));
            pa[n >> 1][(n & 1) ? 2 : 0] = e0;
            pa[n >> 1][(n & 1) ? 3 : 1] = e1;
        }

        float rsum[4] = {0.f, 0.f, 0.f, 0.f};
#pragma unroll
        for (int kk = 0; kk < 4; kk++)
            mma_f16(rsum, pa[kk], H2_ONES, H2_ONES);

        lrow[0] = lrow[0] * a0 + rsum[0];
        lrow[1] = lrow[1] * a1 + rsum[2];

#pragma unroll
        for (int n = 0; n < 8; n++) {
            Oc[n][0] *= a0; Oc[n][1] *= a0;
            Oc[n][2] *= a1; Oc[n][3] *= a1;
        }

        const uint32_t vb0 = sV0 + slot * TSLOT + swz0;
        const uint32_t vb1 = sV0 + slot * TSLOT + swz1;
#pragma unroll
        for (int nd = 0; nd < 8; nd++) {
            uint32_t b00, b01, b10, b11, b20, b21, b30, b31;
            ldsm_x4(b00, b01, b10, b11, vb0 + nd * 1024);
            ldsm_x4(b20, b21, b30, b31, vb1 + nd * 1024);
            mma_f16(Oc[nd], pa[0], b00, b01);
            mma_f16(Oc[nd], pa[1], b10, b11);
            mma_f16(Oc[nd], pa[2], b20, b21);
            mma_f16(Oc[nd], pa[3], b30, b31);
        }
    };

    const int ktmax = qt * 2 + 1;
    const int npre = (ktmax < 3) ? ktmax : 3;
    for (int t = 0; t <= npre; t++) load_kv(t, t);

    int st = 0;
    for (int p = 0; p <= qt; p++) {
        const int t0 = 2 * p;
        if (p < qt) asm volatile("cp.async.wait_group 2;");
        else        asm volatile("cp.async.wait_group 0;");
        __syncthreads();   // pair t0,t0+1 visible; all warps done with pair p-1

        if (p + 2 <= qt) {
            int s4 = st + 4; if (s4 >= 6) s4 -= 6;
            int s5 = st + 5; if (s5 >= 6) s5 -= 6;
            load_kv(s4, t0 + 4);
            load_kv(s5, t0 + 5);
        }

        body(st, t0);
        int s1 = st + 1; if (s1 >= 6) s1 -= 6;
        body(s1, t0 + 1);

        st += 2; if (st >= 6) st -= 6;
    }

    float inv0 = 1.f / lrow[0];
    float inv1 = 1.f / lrow[1];
    __half* Cb0 = g_Ctxh + ((size_t)(b * SS + q0w + g) * DD + h * 64);
    __half* Cb1 = g_Ctxh + ((size_t)(b * SS + q0w + g + 8) * DD + h * 64);
#pragma unroll
    for (int nd = 0; nd < 8; nd++) {
        int col = nd * 8 + 2 * c;
        *(uint32_t*)(Cb0 + col) = packh2(Oc[nd][0] * inv0, Oc[nd][1] * inv0);
        *(uint32_t*)(Cb1 + col) = packh2(Oc[nd][2] * inv1, Oc[nd][3] * inv1);
    }
}

// ---------------------------------------------------------------------------
extern "C" void kernel_launch(void* const* d_in, const int* in_sizes, int n_in,
                              void* d_out, int out_size)
{
    const float* x  = (const float*)d_in[0];
    const float* Wq = (const float*)d_in[1];
    const float* Wk = (const float*)d_in[2];
    const float* Wv = (const float*)d_in[3];
    const float* Wo = (const float*)d_in[4];
    const int* pos  = (const int*)d_in[5];
    float* out = (float*)d_out;

    void* xh_ptr = nullptr, *ctxh_ptr = nullptr;
    cudaGetSymbolAddress(&xh_ptr, g_xh);
    cudaGetSymbolAddress(&ctxh_ptr, g_Ctxh);
    __half* xh = (__half*)xh_ptr;

    static int attr_set = 0;
    if (!attr_set) {
        cudaFuncSetAttribute(gemm3_kernel<0>,
                             cudaFuncAttributeMaxDynamicSharedMemorySize, GSMEM_TOTAL);
        cudaFuncSetAttribute(gemm3_kernel<1>,
                             cudaFuncAttributeMaxDynamicSharedMemorySize, GSMEM_TOTAL);
        cudaFuncSetAttribute(attn_kernel,
                             cudaFuncAttributeMaxDynamicSharedMemorySize, ASMEM_TOTAL);
        attr_set = 1;
    }

    cvt4_kernel<<<2048, 256>>>(x, xh);
    {
        dim3 cg(256, 1, 4);
        cvtw4_kernel<<<cg, 256>>>(Wq, Wk, Wv, Wo);
    }

    dim3 gq(DD / 128, M_TOTAL / 128, 3);   // 8 x 64 x 3
    gemm3_kernel<0><<<gq, 256, GSMEM_TOTAL>>>(xh, nullptr, pos);

    dim3 agrid(SS / 128, HH, BB);
    attn_kernel<<<agrid, 256, ASMEM_TOTAL>>>();

    dim3 go(DD / 128, M_TOTAL / 128);      // 8 x 64
    gemm3_kernel<1><<<go, 256, GSMEM_TOTAL>>>((const __half*)ctxh_ptr, out, pos);
}